// round 10
// baseline (speedup 1.0000x reference)
#include <cuda_runtime.h>
#include <cuda_fp16.h>
#include <math.h>
#include <stdint.h>

#define NB   16
#define CIN  1024
#define CMID 256
#define C8   32
#define HH   48
#define WW   48
#define HW   (HH*WW)
#define NTOT (NB*HW)
#define OCH  512
#define NCLS 21
#define QKVC 384
#define NEG_INF (__int_as_float(0xff800000))

// ---------------- static scratch ----------------
__device__ float g_t0[NB*CMID*HW];
__device__ float g_cc[NB*CMID*HW];
__device__ float g_my[NB*CMID*HW];
__device__ float g_t1[NB*CMID*HW];
__device__ float g_qkv[(size_t)NB*QKVC*HW];
__device__ float g_h [NB*OCH*HW];
__device__ float g_stats[2*OCH];
__device__ float g_S[256];
__device__ float g_Wm[256];
__device__ float g_att[(size_t)NTOT*96];
__device__ float g_Bcc[QKVC];
__device__ float g_Bmy[QKVC];

__device__ __align__(256) __half g_XCh[(size_t)NTOT*1536];
__device__ __align__(256) __half g_XCl[(size_t)NTOT*1536];
__device__ __align__(256) __half g_ACTh[(size_t)NTOT*256];
__device__ __align__(256) __half g_ACTl[(size_t)NTOT*256];
__device__ __align__(256) __half g_WA [256*9216];
__device__ __align__(256) __half g_WM1[256*9216];
__device__ __align__(256) __half g_WB [256*2304];
__device__ __align__(256) __half g_WM2[256*2304];
__device__ __align__(256) __half g_WC [512*13824];
__device__ __align__(256) __half g_WQcc[QKVC*256];
__device__ __align__(256) __half g_WQmy[QKVC*256];

// ---------------- helpers ----------------
__device__ __forceinline__ uint32_t smem_u32(const void* p){
    uint32_t a;
    asm("{ .reg .u64 t; cvta.to.shared.u64 t, %1; cvt.u32.u64 %0, t; }" : "=r"(a) : "l"(p));
    return a;
}
__device__ __forceinline__ void cp16(uint32_t s, const void* g, uint32_t sz){
    asm volatile("cp.async.cg.shared.global [%0], [%1], 16, %2;" :: "r"(s), "l"(g), "r"(sz) : "memory");
}
__device__ __forceinline__ void ldmx4(uint32_t* r, uint32_t a){
    asm volatile("ldmatrix.sync.aligned.m8n8.x4.shared.b16 {%0,%1,%2,%3}, [%4];"
        : "=r"(r[0]),"=r"(r[1]),"=r"(r[2]),"=r"(r[3]) : "r"(a));
}
__device__ __forceinline__ void mma_f16(float* d, const uint32_t* a, const uint32_t* b){
    asm volatile("mma.sync.aligned.m16n8k16.row.col.f32.f16.f16.f32 "
        "{%0,%1,%2,%3}, {%4,%5,%6,%7}, {%8,%9}, {%0,%1,%2,%3};"
        : "+f"(d[0]),"+f"(d[1]),"+f"(d[2]),"+f"(d[3])
        : "r"(a[0]),"r"(a[1]),"r"(a[2]),"r"(a[3]), "r"(b[0]),"r"(b[1]));
}

// ---------------- NCHW fp32 -> NHWC fp16 hi/lo ----------------
__global__ void to_nhwc_kernel(const float* __restrict__ src,
                               __half* __restrict__ hi,
                               __half* __restrict__ lo,
                               int C, int RS, int co)
{
    __shared__ float t[32][33];
    int hw0 = blockIdx.x * 32, c0 = blockIdx.y * 32, b = blockIdx.z;
    int lx = threadIdx.x, ly = threadIdx.y;
    for (int i = ly; i < 32; i += 8)
        t[i][lx] = src[((size_t)(b * C + c0 + i)) * HW + hw0 + lx];
    __syncthreads();
    for (int i = ly; i < 32; i += 8){
        float v = t[lx][i];
        __half h = __float2half_rn(v);
        size_t o = ((size_t)(b * HW + hw0 + i)) * RS + co + c0 + lx;
        hi[o] = h;
        lo[o] = __float2half_rn(v - __half2float(h));
    }
}

__global__ void bn_to_nhwc_kernel(const float* __restrict__ src,
                                  const float* __restrict__ stats,
                                  __half* __restrict__ hi,
                                  __half* __restrict__ lo,
                                  int C, int RS, int co)
{
    __shared__ float t[32][33];
    int hw0 = blockIdx.x * 32, c0 = blockIdx.y * 32, b = blockIdx.z;
    int lx = threadIdx.x, ly = threadIdx.y;
    for (int i = ly; i < 32; i += 8){
        int c = c0 + i;
        float v = src[((size_t)(b * C + c)) * HW + hw0 + lx];
        t[i][lx] = fmaxf(fmaf(v, stats[2*c], stats[2*c+1]), 0.f);
    }
    __syncthreads();
    for (int i = ly; i < 32; i += 8){
        float v = t[lx][i];
        __half h = __float2half_rn(v);
        size_t o = ((size_t)(b * HW + hw0 + i)) * RS + co + c0 + lx;
        hi[o] = h;
        lo[o] = __float2half_rn(v - __half2float(h));
    }
}

// ---------------- weight prep (fp16 hi only) ----------------
__global__ void wprep_kernel(const float* __restrict__ w,
                             __half* __restrict__ hi,
                             int M, int C, int ntaps)
{
    int i = blockIdx.x * 256 + threadIdx.x;
    int Kt = ntaps * C;
    if (i < M * Kt){
        int m = i / Kt; int rest = i - m * Kt; int t = rest / C; int c = rest - t * C;
        hi[i] = __float2half_rn(w[(size_t)(m * C + c) * ntaps + t]);
    }
}

__global__ void wprep_qkv_kernel(const float* __restrict__ qw, const float* __restrict__ qb,
                                 const float* __restrict__ kw, const float* __restrict__ kb,
                                 const float* __restrict__ vw, const float* __restrict__ vb,
                                 __half* __restrict__ hi,
                                 float* __restrict__ bias)
{
    int i = blockIdx.x * 256 + threadIdx.x;
    if (i < QKVC * 256){
        int m = i >> 8, c = i & 255;
        float v = 0.f;
        if (m < 32)       v = qw[m * 256 + c];
        else if (m < 64)  v = kw[(m - 32) * 256 + c];
        else if (m < 320) v = vw[(m - 64) * 256 + c];
        hi[i] = __float2half_rn(v);
    }
    if (i < QKVC){
        float bv = 0.f;
        if (i < 32)       bv = qb[i];
        else if (i < 64)  bv = kb[i - 32];
        else if (i < 320) bv = vb[i - 64];
        bias[i] = bv;
    }
}

// ---------------- mma.sync implicit-GEMM conv ----------------
// Block tile 128(M) x 256(N pixels) x 32(K); 8 warps as 2M x 4N, warp 64x64.
// Smem/buffer: A 128x80 (10240) + Bh 256x80 (20480) + Bl (20480) = 51200; x2.
#define MC_BUF  51200
#define MC_SMEM (2*MC_BUF)   // 102400

struct McCtx {
    const __half *A, *Bh, *Bl;
    int C, ntaps, Ktot, cpT, RS, co;
    int r, half, am;        // A mapping (row = tid>>1, half = tid&1)
    int b, yy, xx;          // B pixel for row = tid
    uint32_t sb;
};

__device__ __forceinline__ void mc_load(const McCtx& cx, int cc, int buf)
{
    int t   = cc / cx.cpT;
    int ci0 = (cc - t * cx.cpT) << 5;
    uint32_t bb = cx.sb + buf * MC_BUF;
    {   // A hi only: (row, half) -> 32 B
        uint32_t dst = bb + cx.r * 80 + cx.half * 32;
        size_t off = (size_t)cx.am * cx.Ktot + t * cx.C + ci0 + cx.half * 16;
        cp16(dst,      cx.A + off,     16);
        cp16(dst + 16, cx.A + off + 8, 16);
    }
    {   // B hi + lo: row = tid -> 64 B each
        int dy = 0, dx = 0;
        if (cx.ntaps == 9){ dy = t / 3 - 1; dx = t - (t / 3) * 3 - 1; }
        int ys = cx.yy + dy, xs = cx.xx + dx;
        bool bv = (ys >= 0 && ys < HH && xs >= 0 && xs < WW);
        size_t off = bv ? ((size_t)(cx.b * HW + ys * WW + xs) * cx.RS + cx.co + ci0) : 0;
        uint32_t sz = bv ? 16u : 0u;
        int tid = cx.r * 2 + cx.half;
        uint32_t dsth = bb + 10240 + (uint32_t)tid * 80;
        uint32_t dstl = dsth + 20480;
#pragma unroll
        for (int i = 0; i < 4; i++){
            cp16(dsth + i * 16, cx.Bh + off + i * 8, sz);
            cp16(dstl + i * 16, cx.Bl + off + i * 8, sz);
        }
    }
}

__global__ __launch_bounds__(256) void mma_conv_kernel(
    const __half* __restrict__ A,
    const __half* __restrict__ Bh, const __half* __restrict__ Bl,
    int M, int C, int ntaps, int RS, int co,
    const float* __restrict__ bias,
    float* __restrict__ out)
{
    extern __shared__ char dynsm[];
    const int tid = threadIdx.x, lane = tid & 31, wid = tid >> 5;
    const int wm = wid & 1, wn = wid >> 1;
    const int m0 = blockIdx.y * 128;
    const int n0 = blockIdx.x * 256;

    McCtx cx;
    cx.A = A; cx.Bh = Bh; cx.Bl = Bl;
    cx.C = C; cx.ntaps = ntaps; cx.Ktot = ntaps * C; cx.cpT = C >> 5;
    cx.RS = RS; cx.co = co;
    cx.r = tid >> 1; cx.half = tid & 1;
    {
        int n = n0 + tid;           // B row for this thread
        cx.b = n / HW;
        int hw = n - cx.b * HW;
        cx.yy = hw / WW;
        cx.xx = hw - cx.yy * WW;
    }
    cx.am = m0 + cx.r;
    cx.sb = smem_u32(dynsm);

    float acc[4][8][4];
#pragma unroll
    for (int i = 0; i < 4; i++)
#pragma unroll
        for (int j = 0; j < 8; j++)
#pragma unroll
            for (int q = 0; q < 4; q++) acc[i][j][q] = 0.f;

    const int NC = cx.Ktot >> 5;

    mc_load(cx, 0, 0);
    asm volatile("cp.async.commit_group;" ::: "memory");

    const uint32_t aRowOff = (uint32_t)(lane & 15) * 80;
    const uint32_t aColOff = (uint32_t)(lane >> 4) * 16;
    const uint32_t bRowOff = (uint32_t)((lane & 7) + ((lane >> 4) << 3)) * 80;
    const uint32_t bColOff = (uint32_t)((lane >> 3) & 1) * 16;

    for (int cc = 0; cc < NC; cc++){
        int buf = cc & 1;
        if (cc + 1 < NC){
            mc_load(cx, cc + 1, (cc + 1) & 1);
            asm volatile("cp.async.commit_group;" ::: "memory");
            asm volatile("cp.async.wait_group 1;" ::: "memory");
        } else {
            asm volatile("cp.async.wait_group 0;" ::: "memory");
        }
        __syncthreads();
        uint32_t base = cx.sb + buf * MC_BUF;
#pragma unroll
        for (int k16 = 0; k16 < 2; k16++){
            uint32_t ac = (uint32_t)k16 * 32 + aColOff;
            uint32_t bc = (uint32_t)k16 * 32 + bColOff;
            uint32_t ah[4][4];
#pragma unroll
            for (int mi = 0; mi < 4; mi++){
                uint32_t ad = base + (uint32_t)(wm * 64 + mi * 16) * 80 + aRowOff + ac;
                ldmx4(ah[mi], ad);
            }
#pragma unroll
            for (int ng = 0; ng < 4; ng++){
                uint32_t bh4[4], bl4[4];
                uint32_t bd = base + 10240 + (uint32_t)(wn * 64 + ng * 16) * 80 + bRowOff + bc;
                ldmx4(bh4, bd);
                ldmx4(bl4, bd + 20480);
#pragma unroll
                for (int mi = 0; mi < 4; mi++){
#pragma unroll
                    for (int nh = 0; nh < 2; nh++){
                        float* ac4 = acc[mi][ng * 2 + nh];
                        mma_f16(ac4, ah[mi], &bh4[nh * 2]);
                        mma_f16(ac4, ah[mi], &bl4[nh * 2]);
                    }
                }
            }
        }
        __syncthreads();
    }

    int tb = n0 / HW;
    int hw0 = n0 - tb * HW;
#pragma unroll
    for (int mi = 0; mi < 4; mi++){
        int mrow = m0 + wm * 64 + mi * 16 + (lane >> 2);
        float b0 = bias ? __ldg(bias + mrow)     : 0.f;
        float b1 = bias ? __ldg(bias + mrow + 8) : 0.f;
#pragma unroll
        for (int ni = 0; ni < 8; ni++){
            int col = hw0 + wn * 64 + ni * 8 + (lane & 3) * 2;
            float2 v0 = make_float2(acc[mi][ni][0] + b0, acc[mi][ni][1] + b0);
            float2 v1 = make_float2(acc[mi][ni][2] + b1, acc[mi][ni][3] + b1);
            *(float2*)&out[((size_t)(tb * M + mrow)) * HW + col]     = v0;
            *(float2*)&out[((size_t)(tb * M + mrow + 8)) * HW + col] = v1;
        }
    }
}

// ---------------- fp32 GEMM (classifier only) ----------------
__global__ __launch_bounds__(256) void gemm_conv_kernel(
    const float* __restrict__ Wt, const float* __restrict__ p0,
    int M, int Cin, const float* __restrict__ bias, float* __restrict__ out)
{
    __shared__ float As[16][128];
    __shared__ float Bs[16][128];
    const int tid = threadIdx.x;
    const int tx = tid & 15, ty = tid >> 4;
    const int m0 = blockIdx.y * 128;
    const int n0 = blockIdx.x * 128;
    float acc[8][8];
#pragma unroll
    for (int i = 0; i < 8; i++)
#pragma unroll
        for (int j = 0; j < 8; j++) acc[i][j] = 0.f;
    const int nl = tid & 127;
    const int nglob = n0 + nl;
    const int bb = nglob / HW;
    const int hw = nglob - bb * HW;
    const int kbB = (tid >> 7) * 8;
    const int ml = tid >> 1;
    const int kbA = (tid & 1) * 8;
    for (int k0 = 0; k0 < Cin; k0 += 16){
        int m = m0 + ml;
        const float* wp = Wt + (size_t)m * Cin + (k0 + kbA);
#pragma unroll
        for (int i = 0; i < 8; i++)
            As[kbA + i][ml] = (m < M) ? wp[i] : 0.f;
#pragma unroll
        for (int i = 0; i < 8; i++)
            Bs[kbB + i][nl] = p0[((size_t)(bb * Cin + k0 + kbB + i)) * HW + hw];
        __syncthreads();
#pragma unroll
        for (int kk = 0; kk < 16; kk++){
            float a[8], bq[8];
#pragma unroll
            for (int i = 0; i < 8; i++) a[i]  = As[kk][ty + 16 * i];
#pragma unroll
            for (int j = 0; j < 8; j++) bq[j] = Bs[kk][tx + 16 * j];
#pragma unroll
            for (int i = 0; i < 8; i++)
#pragma unroll
                for (int j = 0; j < 8; j++)
                    acc[i][j] = fmaf(a[i], bq[j], acc[i][j]);
        }
        __syncthreads();
    }
#pragma unroll
    for (int i = 0; i < 8; i++){
        int m = m0 + ty + 16 * i;
        if (m >= M) continue;
        float bval = bias ? bias[m] : 0.f;
#pragma unroll
        for (int j = 0; j < 8; j++){
            int n = n0 + tx + 16 * j;
            int b = n / HW;
            int hw2 = n - b * HW;
            out[((size_t)(b * M + m)) * HW + hw2] = acc[i][j] + bval;
        }
    }
}

// ---------------- BatchNorm ----------------
__global__ void bn_stats_kernel(const float* __restrict__ x,
                                const float* __restrict__ g,
                                const float* __restrict__ bta,
                                float* __restrict__ stats, int C)
{
    int c = blockIdx.x, tid = threadIdx.x;
    float s = 0.f, sq = 0.f;
    for (int i = tid; i < NB * HW; i += 256){
        int bb = i / HW;
        float v = x[((size_t)(bb * C + c)) * HW + (i - bb * HW)];
        s += v; sq += v * v;
    }
    __shared__ float sh1[256], sh2[256];
    sh1[tid] = s; sh2[tid] = sq;
    __syncthreads();
    for (int st = 128; st; st >>= 1){
        if (tid < st){ sh1[tid] += sh1[tid + st]; sh2[tid] += sh2[tid + st]; }
        __syncthreads();
    }
    if (tid == 0){
        float n = (float)(NB * HW);
        float m = sh1[0] / n;
        float var = sh2[0] / n - m * m;
        float sc = g[c] * rsqrtf(var + 1e-5f);
        stats[2 * c] = sc;
        stats[2 * c + 1] = bta[c] - m * sc;
    }
}

__global__ void bn_apply_kernel(const float* __restrict__ x,
                                const float* __restrict__ stats,
                                float* __restrict__ y, int C, int total)
{
    int i = blockIdx.x * 256 + threadIdx.x;
    if (i < total){
        int c = (i / HW) % C;
        y[i] = fmaxf(fmaf(x[i], stats[2 * c], stats[2 * c + 1]), 0.f);
    }
}

// ---------------- criss-cross attention ----------------
__global__ void cc_logits_col_kernel(const float* __restrict__ qkv,
                                     float* __restrict__ att)
{
    int w = blockIdx.x, b = blockIdx.y, tid = threadIdx.x;
    __shared__ float qs[32][48], ks[32][48];
    for (int i = tid; i < 32 * 48; i += 256){
        int c = i / 48, h = i - (i / 48) * 48;
        qs[c][h] = qkv[((size_t)((b * QKVC + c) * 48 + h)) * 48 + w];
        ks[c][h] = qkv[((size_t)((b * QKVC + 32 + c) * 48 + h)) * 48 + w];
    }
    __syncthreads();
    for (int i = tid; i < 48 * 48; i += 256){
        int h = i / 48, g = i - (i / 48) * 48;
        float s;
        if (g == h) s = NEG_INF;
        else {
            s = 0.f;
#pragma unroll
            for (int c = 0; c < 32; c++) s += qs[c][h] * ks[c][g];
        }
        att[((size_t)((b * 48 + h) * 48 + w)) * 96 + g] = s;
    }
}

__global__ void cc_logits_row_kernel(const float* __restrict__ qkv,
                                     float* __restrict__ att)
{
    int h = blockIdx.x, b = blockIdx.y, tid = threadIdx.x;
    __shared__ float qs[32][48], ks[32][48];
    for (int i = tid; i < 32 * 48; i += 256){
        int c = i / 48, w = i - (i / 48) * 48;
        qs[c][w] = qkv[((size_t)((b * QKVC + c) * 48 + h)) * 48 + w];
        ks[c][w] = qkv[((size_t)((b * QKVC + 32 + c) * 48 + h)) * 48 + w];
    }
    __syncthreads();
    for (int i = tid; i < 48 * 48; i += 256){
        int w = i / 48, v2 = i - (i / 48) * 48;
        float s = 0.f;
#pragma unroll
        for (int c = 0; c < 32; c++) s += qs[c][w] * ks[c][v2];
        att[((size_t)((b * 48 + h) * 48 + w)) * 96 + 48 + v2] = s;
    }
}

__global__ void cc_softmax_kernel(float* __restrict__ att)
{
    int row  = blockIdx.x * 8 + (threadIdx.x >> 5);
    int lane = threadIdx.x & 31;
    float* p = att + (size_t)row * 96;
    float v0 = p[lane], v1 = p[lane + 32], v2 = p[lane + 64];
    float mx = fmaxf(v0, fmaxf(v1, v2));
#pragma unroll
    for (int off = 16; off; off >>= 1) mx = fmaxf(mx, __shfl_xor_sync(0xffffffff, mx, off));
    float e0 = expf(v0 - mx), e1 = expf(v1 - mx), e2 = expf(v2 - mx);
    float s = e0 + e1 + e2;
#pragma unroll
    for (int off = 16; off; off >>= 1) s += __shfl_xor_sync(0xffffffff, s, off);
    float inv = 1.f / s;
    p[lane] = e0 * inv; p[lane + 32] = e1 * inv; p[lane + 64] = e2 * inv;
}

#define CC_SMEM ((256*48 + 48*48) * 4)

__global__ void cc_out_col_kernel(const float* __restrict__ qkv,
                                  const float* __restrict__ att,
                                  const float* __restrict__ xin,
                                  const float* __restrict__ gamma,
                                  float* __restrict__ out)
{
    extern __shared__ float cs[];
    float* vs = cs; float* as = cs + 256 * 48;
    int w = blockIdx.x, b = blockIdx.y, tid = threadIdx.x;
    for (int i = tid; i < 256 * 48; i += 256){
        int c = i / 48, g = i - (i / 48) * 48;
        vs[i] = qkv[((size_t)((b * QKVC + 64 + c) * 48 + g)) * 48 + w];
    }
    for (int i = tid; i < 48 * 48; i += 256){
        int h = i / 48, g = i - (i / 48) * 48;
        as[i] = att[((size_t)((b * 48 + h) * 48 + w)) * 96 + g];
    }
    __syncthreads();
    float gm = gamma[0];
    for (int i = tid; i < 256 * 48; i += 256){
        int c = i / 48, h = i - (i / 48) * 48;
        float s = 0.f;
#pragma unroll
        for (int g = 0; g < 48; g++) s += vs[c * 48 + g] * as[h * 48 + g];
        size_t o = ((size_t)((b * 256 + c) * 48 + h)) * 48 + w;
        out[o] = xin[o] + gm * s;
    }
}

__global__ void cc_out_row_kernel(const float* __restrict__ qkv,
                                  const float* __restrict__ att,
                                  const float* __restrict__ gamma,
                                  float* __restrict__ out)
{
    extern __shared__ float cs[];
    float* vs = cs; float* as = cs + 256 * 48;
    int h = blockIdx.x, b = blockIdx.y, tid = threadIdx.x;
    for (int i = tid; i < 256 * 48; i += 256){
        vs[i] = qkv[((size_t)(b * QKVC + 64 + i / 48) * 48 + h) * 48 + (i % 48)];
    }
    for (int i = tid; i < 48 * 48; i += 256){
        int w2 = i / 48, v2 = i - (i / 48) * 48;
        as[i] = att[((size_t)((b * 48 + h) * 48 + w2)) * 96 + 48 + v2];
    }
    __syncthreads();
    float gm = gamma[0];
    for (int i = tid; i < 256 * 48; i += 256){
        int c = i / 48, w2 = i - (i / 48) * 48;
        float s = 0.f;
#pragma unroll
        for (int v2 = 0; v2 < 48; v2++) s += vs[c * 48 + v2] * as[w2 * 48 + v2];
        size_t o = ((size_t)((b * 256 + c) * 48 + h)) * 48 + w2;
        out[o] += gm * s;
    }
}

// ---------------- grid attention ----------------
__global__ void gram_kernel(const float* __restrict__ qkv,
                            float* __restrict__ S)
{
    int b1 = blockIdx.x >> 4, b2 = blockIdx.x & 15;
    const float* qp = qkv + (size_t)b1 * (QKVC * HW);
    const float* kp = qkv + (size_t)b2 * (QKVC * HW) + 32 * HW;
    int tid = threadIdx.x;
    float s = 0.f;
    for (int i = tid; i < C8 * HW; i += 256) s += qp[i] * kp[i];
    __shared__ float sh[256];
    sh[tid] = s;
    __syncthreads();
    for (int st = 128; st; st >>= 1){
        if (tid < st) sh[tid] += sh[tid + st];
        __syncthreads();
    }
    if (tid == 0) S[blockIdx.x] = sh[0];
}

__global__ void myw_kernel(const float* __restrict__ S, float* __restrict__ Wm)
{
    int b1 = threadIdx.x;
    if (b1 < 16){
        int gh = b1 >> 2, gw = b1 & 3;
        float l[8];
        for (int j = 0; j < 4; j++){
            int b2 = j * 4 + gw;
            l[j] = (j == gh) ? NEG_INF : S[b1 * 16 + b2];
        }
        for (int j = 0; j < 4; j++) l[4 + j] = S[b1 * 16 + gh * 4 + j];
        float mx = NEG_INF;
        for (int j = 0; j < 8; j++) mx = fmaxf(mx, l[j]);
        float sm = 0.f;
        for (int j = 0; j < 8; j++){ l[j] = expf(l[j] - mx); sm += l[j]; }
        float inv = 1.f / sm;
        float w[16];
        for (int i = 0; i < 16; i++) w[i] = 0.f;
        for (int j = 0; j < 4; j++) w[j * 4 + gw] += l[j] * inv;
        for (int j = 0; j < 4; j++) w[gh * 4 + j] += l[4 + j] * inv;
        for (int i = 0; i < 16; i++) Wm[b1 * 16 + i] = w[i];
    }
}

__global__ void my_combine_kernel(const float* __restrict__ qkv,
                                  const float* __restrict__ Wm,
                                  const float* __restrict__ xin,
                                  const float* __restrict__ gamma,
                                  float* __restrict__ out)
{
    __shared__ float ws[256];
    if (threadIdx.x < 256) ws[threadIdx.x] = Wm[threadIdx.x];
    __syncthreads();
    const int PB = CMID * HW;
    int n = blockIdx.x * 256 + threadIdx.x;
    if (n < PB){
        float vv[16];
#pragma unroll
        for (int b = 0; b < 16; b++)
            vv[b] = qkv[(size_t)b * (QKVC * HW) + 64 * HW + n];
        float gm = gamma[0];
#pragma unroll
        for (int b1 = 0; b1 < 16; b1++){
            float o = 0.f;
#pragma unroll
            for (int b2 = 0; b2 < 16; b2++) o += ws[b1 * 16 + b2] * vv[b2];
            out[(size_t)b1 * PB + n] = gm * o + xin[(size_t)b1 * PB + n];
        }
    }
}

// ---------------- host ----------------
extern "C" void kernel_launch(void* const* d_in, const int* in_sizes, int n_in,
                              void* d_out, int out_size)
{
    const float* x      = (const float*)d_in[0];
    const float* w_a    = (const float*)d_in[1];
    const float* g_a    = (const float*)d_in[2];
    const float* b_a    = (const float*)d_in[3];
    const float* ccq_w  = (const float*)d_in[4];
    const float* ccq_b  = (const float*)d_in[5];
    const float* cck_w  = (const float*)d_in[6];
    const float* cck_b  = (const float*)d_in[7];
    const float* ccv_w  = (const float*)d_in[8];
    const float* ccv_b  = (const float*)d_in[9];
    const float* cc_gm  = (const float*)d_in[10];
    const float* w_b    = (const float*)d_in[11];
    const float* g_b    = (const float*)d_in[12];
    const float* b_b    = (const float*)d_in[13];
    const float* w_m1   = (const float*)d_in[14];
    const float* g_m1   = (const float*)d_in[15];
    const float* b_m1   = (const float*)d_in[16];
    const float* myq_w  = (const float*)d_in[17];
    const float* myq_b  = (const float*)d_in[18];
    const float* myk_w  = (const float*)d_in[19];
    const float* myk_b  = (const float*)d_in[20];
    const float* myv_w  = (const float*)d_in[21];
    const float* myv_b  = (const float*)d_in[22];
    const float* my_gm  = (const float*)d_in[23];
    const float* w_m2   = (const float*)d_in[24];
    const float* g_m2   = (const float*)d_in[25];
    const float* b_m2   = (const float*)d_in[26];
    const float* w_c    = (const float*)d_in[27];
    const float* g_c    = (const float*)d_in[28];
    const float* b_c    = (const float*)d_in[29];
    const float* w_cls  = (const float*)d_in[30];
    const float* b_cls  = (const float*)d_in[31];

    cudaFuncSetAttribute(mma_conv_kernel, cudaFuncAttributeMaxDynamicSharedMemorySize, MC_SMEM);
    cudaFuncSetAttribute(cc_out_col_kernel, cudaFuncAttributeMaxDynamicSharedMemorySize, CC_SMEM);
    cudaFuncSetAttribute(cc_out_row_kernel, cudaFuncAttributeMaxDynamicSharedMemorySize, CC_SMEM);

    float *pt0, *pcc, *pmy, *pt1, *pqkv, *ph, *pst, *pS, *pWm, *patt, *pBcc, *pBmy;
    cudaGetSymbolAddress((void**)&pt0, g_t0);
    cudaGetSymbolAddress((void**)&pcc, g_cc);
    cudaGetSymbolAddress((void**)&pmy, g_my);
    cudaGetSymbolAddress((void**)&pt1, g_t1);
    cudaGetSymbolAddress((void**)&pqkv, g_qkv);
    cudaGetSymbolAddress((void**)&ph,  g_h);
    cudaGetSymbolAddress((void**)&pst, g_stats);
    cudaGetSymbolAddress((void**)&pS,  g_S);
    cudaGetSymbolAddress((void**)&pWm, g_Wm);
    cudaGetSymbolAddress((void**)&patt, g_att);
    cudaGetSymbolAddress((void**)&pBcc, g_Bcc);
    cudaGetSymbolAddress((void**)&pBmy, g_Bmy);

    __half *XCh,*XCl,*ACTh,*ACTl;
    __half *WA,*WM1,*WB,*WM2,*WC,*WQcc,*WQmy;
    cudaGetSymbolAddress((void**)&XCh, g_XCh);   cudaGetSymbolAddress((void**)&XCl, g_XCl);
    cudaGetSymbolAddress((void**)&ACTh, g_ACTh); cudaGetSymbolAddress((void**)&ACTl, g_ACTl);
    cudaGetSymbolAddress((void**)&WA, g_WA);
    cudaGetSymbolAddress((void**)&WM1, g_WM1);
    cudaGetSymbolAddress((void**)&WB, g_WB);
    cudaGetSymbolAddress((void**)&WM2, g_WM2);
    cudaGetSymbolAddress((void**)&WC, g_WC);
    cudaGetSymbolAddress((void**)&WQcc, g_WQcc);
    cudaGetSymbolAddress((void**)&WQmy, g_WQmy);

    const dim3 blk(256);
    const dim3 tr_blk(32, 8);
    const int NT2 = NTOT / 256;   // 144 N-tiles (256 pixels each)
    const int NT  = NTOT / 128;   // classifier fp32 gemm
    const int TOT_MID = NB*CMID*HW;

    // weight prep
    wprep_kernel<<<(256*9216 + 255)/256, blk>>>(w_a,  WA,  256, 1024, 9);
    wprep_kernel<<<(256*9216 + 255)/256, blk>>>(w_m1, WM1, 256, 1024, 9);
    wprep_kernel<<<(256*2304 + 255)/256, blk>>>(w_b,  WB,  256, 256, 9);
    wprep_kernel<<<(256*2304 + 255)/256, blk>>>(w_m2, WM2, 256, 256, 9);
    wprep_kernel<<<(512*13824 + 255)/256, blk>>>(w_c, WC,  512, 1536, 9);
    wprep_qkv_kernel<<<(QKVC*256 + 255)/256, blk>>>(ccq_w, ccq_b, cck_w, cck_b, ccv_w, ccv_b,
                                                    WQcc, pBcc);
    wprep_qkv_kernel<<<(QKVC*256 + 255)/256, blk>>>(myq_w, myq_b, myk_w, myk_b, myv_w, myv_b,
                                                    WQmy, pBmy);

    // x -> XC[0:1024]
    to_nhwc_kernel<<<dim3(HW/32, 1024/32, NB), tr_blk>>>(x, XCh, XCl, 1024, 1536, 0);

    // conv_a, conv_m1
    mma_conv_kernel<<<dim3(NT2, 2), blk, MC_SMEM>>>(WA, XCh, XCl, 256, 1024, 9, 1536, 0, nullptr, pt0);
    bn_stats_kernel<<<CMID, blk>>>(pt0, g_a, b_a, pst, CMID);
    bn_apply_kernel<<<(TOT_MID + 255)/256, blk>>>(pt0, pst, pcc, CMID, TOT_MID);

    mma_conv_kernel<<<dim3(NT2, 2), blk, MC_SMEM>>>(WM1, XCh, XCl, 256, 1024, 9, 1536, 0, nullptr, pt0);
    bn_stats_kernel<<<CMID, blk>>>(pt0, g_m1, b_m1, pst, CMID);
    bn_apply_kernel<<<(TOT_MID + 255)/256, blk>>>(pt0, pst, pmy, CMID, TOT_MID);

    // cc attention x2
    {
        float* ca = pcc; float* cb = pt1;
        for (int it = 0; it < 2; it++){
            to_nhwc_kernel<<<dim3(HW/32, 256/32, NB), tr_blk>>>(ca, ACTh, ACTl, 256, 256, 0);
            mma_conv_kernel<<<dim3(NT2, 3), blk, MC_SMEM>>>(WQcc, ACTh, ACTl,
                                                            QKVC, 256, 1, 256, 0, pBcc, pqkv);
            cc_logits_col_kernel<<<dim3(WW, NB), blk>>>(pqkv, patt);
            cc_logits_row_kernel<<<dim3(HH, NB), blk>>>(pqkv, patt);
            cc_softmax_kernel<<<NTOT/8, blk>>>(patt);
            cc_out_col_kernel<<<dim3(WW, NB), blk, CC_SMEM>>>(pqkv, patt, ca, cc_gm, cb);
            cc_out_row_kernel<<<dim3(HH, NB), blk, CC_SMEM>>>(pqkv, patt, cc_gm, cb);
            float* tmp = ca; ca = cb; cb = tmp;
        }
    }

    // my attention x2
    {
        float* ma = pmy; float* mb = pt1;
        for (int it = 0; it < 2; it++){
            to_nhwc_kernel<<<dim3(HW/32, 256/32, NB), tr_blk>>>(ma, ACTh, ACTl, 256, 256, 0);
            mma_conv_kernel<<<dim3(NT2, 3), blk, MC_SMEM>>>(WQmy, ACTh, ACTl,
                                                            QKVC, 256, 1, 256, 0, pBmy, pqkv);
            gram_kernel<<<256, blk>>>(pqkv, pS);
            myw_kernel<<<1, 32>>>(pS, pWm);
            my_combine_kernel<<<(CMID*HW + 255)/256, blk>>>(pqkv, pWm, ma, my_gm, mb);
            float* tmp = ma; ma = mb; mb = tmp;
        }
    }

    // conv_b: input pcc -> BN -> XC@1024 (fused)
    to_nhwc_kernel<<<dim3(HW/32, 256/32, NB), tr_blk>>>(pcc, ACTh, ACTl, 256, 256, 0);
    mma_conv_kernel<<<dim3(NT2, 2), blk, MC_SMEM>>>(WB, ACTh, ACTl, 256, 256, 9, 256, 0, nullptr, pt0);
    bn_stats_kernel<<<CMID, blk>>>(pt0, g_b, b_b, pst, CMID);
    bn_to_nhwc_kernel<<<dim3(HW/32, 256/32, NB), tr_blk>>>(pt0, pst, XCh, XCl, 256, 1536, 1024);

    // conv_m2: input pmy -> BN -> XC@1280 (fused)
    to_nhwc_kernel<<<dim3(HW/32, 256/32, NB), tr_blk>>>(pmy, ACTh, ACTl, 256, 256, 0);
    mma_conv_kernel<<<dim3(NT2, 2), blk, MC_SMEM>>>(WM2, ACTh, ACTl, 256, 256, 9, 256, 0, nullptr, pt0);
    bn_stats_kernel<<<CMID, blk>>>(pt0, g_m2, b_m2, pst, CMID);
    bn_to_nhwc_kernel<<<dim3(HW/32, 256/32, NB), tr_blk>>>(pt0, pst, XCh, XCl, 256, 1536, 1280);

    // conv_c + BN
    mma_conv_kernel<<<dim3(NT2, 4), blk, MC_SMEM>>>(WC, XCh, XCl, 512, 1536, 9, 1536, 0, nullptr, ph);
    bn_stats_kernel<<<OCH, blk>>>(ph, g_c, b_c, pst, OCH);
    bn_apply_kernel<<<(NB*OCH*HW + 255)/256, blk>>>(ph, pst, ph, OCH, NB*OCH*HW);

    // classifier
    gemm_conv_kernel<<<dim3(NT, 1), blk>>>(w_cls, ph, NCLS, OCH, b_cls, (float*)d_out);
}

// round 14
// speedup vs baseline: 1.2331x; 1.2331x over previous
#include <cuda_runtime.h>
#include <cuda_fp16.h>
#include <math.h>
#include <stdint.h>

#define NB   16
#define CIN  1024
#define CMID 256
#define C8   32
#define HH   48
#define WW   48
#define HW   (HH*WW)
#define NTOT (NB*HW)
#define OCH  512
#define NCLS 21
#define QKVC 384
#define NEG_INF (__int_as_float(0xff800000))

// ---------------- static scratch ----------------
__device__ float g_t0[NB*CMID*HW];
__device__ float g_cc[NB*CMID*HW];
__device__ float g_my[NB*CMID*HW];
__device__ float g_t1[NB*CMID*HW];
__device__ float g_qkv[(size_t)NB*QKVC*HW];
__device__ float g_h [NB*OCH*HW];
__device__ float g_stats[2*OCH];
__device__ float g_S[256];
__device__ float g_Wm[256];
__device__ float g_att[(size_t)NTOT*96];
__device__ float g_Bcc[QKVC];
__device__ float g_Bmy[QKVC];

__device__ __align__(256) __half g_XCh[(size_t)NTOT*1536];
__device__ __align__(256) __half g_XCl[(size_t)NTOT*1536];
__device__ __align__(256) __half g_ACTh[(size_t)NTOT*256];
__device__ __align__(256) __half g_ACTl[(size_t)NTOT*256];
__device__ __align__(256) __half g_WA [256*9216];
__device__ __align__(256) __half g_WM1[256*9216];
__device__ __align__(256) __half g_WB [256*2304];
__device__ __align__(256) __half g_WM2[256*2304];
__device__ __align__(256) __half g_WC [512*13824];
__device__ __align__(256) __half g_WQcc[QKVC*256];
__device__ __align__(256) __half g_WQmy[QKVC*256];

// ---------------- helpers ----------------
__device__ __forceinline__ uint32_t smem_u32(const void* p){
    uint32_t a;
    asm("{ .reg .u64 t; cvta.to.shared.u64 t, %1; cvt.u32.u64 %0, t; }" : "=r"(a) : "l"(p));
    return a;
}
__device__ __forceinline__ void cp16(uint32_t s, const void* g, uint32_t sz){
    asm volatile("cp.async.cg.shared.global [%0], [%1], 16, %2;" :: "r"(s), "l"(g), "r"(sz) : "memory");
}
__device__ __forceinline__ void ldmx4(uint32_t* r, uint32_t a){
    asm volatile("ldmatrix.sync.aligned.m8n8.x4.shared.b16 {%0,%1,%2,%3}, [%4];"
        : "=r"(r[0]),"=r"(r[1]),"=r"(r[2]),"=r"(r[3]) : "r"(a));
}
__device__ __forceinline__ void mma_f16(float* d, const uint32_t* a, const uint32_t* b){
    asm volatile("mma.sync.aligned.m16n8k16.row.col.f32.f16.f16.f32 "
        "{%0,%1,%2,%3}, {%4,%5,%6,%7}, {%8,%9}, {%0,%1,%2,%3};"
        : "+f"(d[0]),"+f"(d[1]),"+f"(d[2]),"+f"(d[3])
        : "r"(a[0]),"r"(a[1]),"r"(a[2]),"r"(a[3]), "r"(b[0]),"r"(b[1]));
}

// ---------------- NCHW fp32 -> NHWC fp16 hi/lo ----------------
__global__ void to_nhwc_kernel(const float* __restrict__ src,
                               __half* __restrict__ hi,
                               __half* __restrict__ lo,
                               int C, int RS, int co)
{
    __shared__ float t[32][33];
    int hw0 = blockIdx.x * 32, c0 = blockIdx.y * 32, b = blockIdx.z;
    int lx = threadIdx.x, ly = threadIdx.y;
    for (int i = ly; i < 32; i += 8)
        t[i][lx] = src[((size_t)(b * C + c0 + i)) * HW + hw0 + lx];
    __syncthreads();
    for (int i = ly; i < 32; i += 8){
        float v = t[lx][i];
        __half h = __float2half_rn(v);
        size_t o = ((size_t)(b * HW + hw0 + i)) * RS + co + c0 + lx;
        hi[o] = h;
        lo[o] = __float2half_rn(v - __half2float(h));
    }
}

__global__ void bn_to_nhwc_kernel(const float* __restrict__ src,
                                  const float* __restrict__ stats,
                                  __half* __restrict__ hi,
                                  __half* __restrict__ lo,
                                  int C, int RS, int co)
{
    __shared__ float t[32][33];
    int hw0 = blockIdx.x * 32, c0 = blockIdx.y * 32, b = blockIdx.z;
    int lx = threadIdx.x, ly = threadIdx.y;
    for (int i = ly; i < 32; i += 8){
        int c = c0 + i;
        float v = src[((size_t)(b * C + c)) * HW + hw0 + lx];
        t[i][lx] = fmaxf(fmaf(v, stats[2*c], stats[2*c+1]), 0.f);
    }
    __syncthreads();
    for (int i = ly; i < 32; i += 8){
        float v = t[lx][i];
        __half h = __float2half_rn(v);
        size_t o = ((size_t)(b * HW + hw0 + i)) * RS + co + c0 + lx;
        hi[o] = h;
        lo[o] = __float2half_rn(v - __half2float(h));
    }
}

// ---------------- weight prep (fp16 hi only) ----------------
__global__ void wprep_kernel(const float* __restrict__ w,
                             __half* __restrict__ hi,
                             int M, int C, int ntaps)
{
    int i = blockIdx.x * 256 + threadIdx.x;
    int Kt = ntaps * C;
    if (i < M * Kt){
        int m = i / Kt; int rest = i - m * Kt; int t = rest / C; int c = rest - t * C;
        hi[i] = __float2half_rn(w[(size_t)(m * C + c) * ntaps + t]);
    }
}

__global__ void wprep_qkv_kernel(const float* __restrict__ qw, const float* __restrict__ qb,
                                 const float* __restrict__ kw, const float* __restrict__ kb,
                                 const float* __restrict__ vw, const float* __restrict__ vb,
                                 __half* __restrict__ hi,
                                 float* __restrict__ bias)
{
    int i = blockIdx.x * 256 + threadIdx.x;
    if (i < QKVC * 256){
        int m = i >> 8, c = i & 255;
        float v = 0.f;
        if (m < 32)       v = qw[m * 256 + c];
        else if (m < 64)  v = kw[(m - 32) * 256 + c];
        else if (m < 320) v = vw[(m - 64) * 256 + c];
        hi[i] = __float2half_rn(v);
    }
    if (i < QKVC){
        float bv = 0.f;
        if (i < 32)       bv = qb[i];
        else if (i < 64)  bv = kb[i - 32];
        else if (i < 320) bv = vb[i - 64];
        bias[i] = bv;
    }
}

// ---------------- mma.sync implicit-GEMM conv (fp16 2-product, 3-stage) -------
#define MC_BUF  30720
#define MC_SMEM (3*MC_BUF)   // 92160 -> 2 CTAs/SM

struct McCtx {
    const __half *A, *Bh, *Bl;
    int C, ntaps, Ktot, cpT, RS, co;
    int r, half, b, yy, xx, am;
    uint32_t sb;
};

__device__ __forceinline__ void mc_load(const McCtx& cx, int cc, int buf)
{
    int t   = cc / cx.cpT;
    int ci0 = (cc - t * cx.cpT) << 5;
    uint32_t dst = cx.sb + buf * MC_BUF + cx.r * 80 + cx.half * 32;
    {
        size_t off = (size_t)cx.am * cx.Ktot + t * cx.C + ci0 + cx.half * 16;
        cp16(dst,      cx.A + off,     16);
        cp16(dst + 16, cx.A + off + 8, 16);
    }
    {
        int dy = 0, dx = 0;
        if (cx.ntaps == 9){ dy = t / 3 - 1; dx = t - (t / 3) * 3 - 1; }
        int ys = cx.yy + dy, xs = cx.xx + dx;
        bool bv = (ys >= 0 && ys < HH && xs >= 0 && xs < WW);
        size_t off = bv ? ((size_t)(cx.b * HW + ys * WW + xs) * cx.RS + cx.co + ci0 + cx.half * 16) : 0;
        uint32_t sz = bv ? 16u : 0u;
        cp16(dst + 10240,      cx.Bh + off,     sz);
        cp16(dst + 10240 + 16, cx.Bh + off + 8, sz);
        cp16(dst + 20480,      cx.Bl + off,     sz);
        cp16(dst + 20480 + 16, cx.Bl + off + 8, sz);
    }
}

__global__ __launch_bounds__(256) void mma_conv_kernel(
    const __half* __restrict__ A,
    const __half* __restrict__ Bh, const __half* __restrict__ Bl,
    int M, int C, int ntaps, int RS, int co,
    const float* __restrict__ bias,
    float* __restrict__ out)
{
    extern __shared__ char dynsm[];
    const int tid = threadIdx.x, lane = tid & 31, wid = tid >> 5;
    const int wm = wid & 1, wn = wid >> 1;
    const int m0 = blockIdx.y * 128;
    const int n0 = blockIdx.x * 128;

    McCtx cx;
    cx.A = A; cx.Bh = Bh; cx.Bl = Bl;
    cx.C = C; cx.ntaps = ntaps; cx.Ktot = ntaps * C; cx.cpT = C >> 5;
    cx.RS = RS; cx.co = co;
    cx.r = tid >> 1; cx.half = tid & 1;
    {
        int n = n0 + cx.r;
        cx.b = n / HW;
        int hw = n - cx.b * HW;
        cx.yy = hw / WW;
        cx.xx = hw - cx.yy * WW;
    }
    cx.am = m0 + cx.r;
    cx.sb = smem_u32(dynsm);

    float acc[4][4][4];
#pragma unroll
    for (int i = 0; i < 4; i++)
#pragma unroll
        for (int j = 0; j < 4; j++)
#pragma unroll
            for (int q = 0; q < 4; q++) acc[i][j][q] = 0.f;

    const int NC = cx.Ktot >> 5;

    mc_load(cx, 0, 0);
    asm volatile("cp.async.commit_group;" ::: "memory");
    if (NC > 1){
        mc_load(cx, 1, 1);
        asm volatile("cp.async.commit_group;" ::: "memory");
    }

    const uint32_t aRowOff = (uint32_t)(lane & 15) * 80;
    const uint32_t aColOff = (uint32_t)(lane >> 4) * 16;
    const uint32_t bRowOff = (uint32_t)((lane & 7) + ((lane >> 4) << 3)) * 80;
    const uint32_t bColOff = (uint32_t)((lane >> 3) & 1) * 16;

    int buf = 0;
    for (int cc = 0; cc < NC; cc++){
        if (cc + 2 < NC){
            int nb = buf + 2; if (nb >= 3) nb -= 3;
            mc_load(cx, cc + 2, nb);
            asm volatile("cp.async.commit_group;" ::: "memory");
            asm volatile("cp.async.wait_group 2;" ::: "memory");
        } else if (cc + 1 < NC){
            asm volatile("cp.async.wait_group 1;" ::: "memory");
        } else {
            asm volatile("cp.async.wait_group 0;" ::: "memory");
        }
        __syncthreads();
        uint32_t base = cx.sb + buf * MC_BUF;
#pragma unroll
        for (int k16 = 0; k16 < 2; k16++){
            uint32_t ac = (uint32_t)k16 * 32 + aColOff;
            uint32_t bc = (uint32_t)k16 * 32 + bColOff;
            uint32_t ah[4][4], bh[2][4], bl[2][4];
#pragma unroll
            for (int mi = 0; mi < 4; mi++){
                uint32_t ad = base + (uint32_t)(wm * 64 + mi * 16) * 80 + aRowOff + ac;
                ldmx4(ah[mi], ad);
            }
#pragma unroll
            for (int ng = 0; ng < 2; ng++){
                uint32_t bd = base + 10240 + (uint32_t)(wn * 32 + ng * 16) * 80 + bRowOff + bc;
                ldmx4(bh[ng], bd);
                ldmx4(bl[ng], bd + 10240);
            }
#pragma unroll
            for (int mi = 0; mi < 4; mi++){
#pragma unroll
                for (int ni = 0; ni < 4; ni++){
                    const uint32_t* bhp = &bh[ni >> 1][(ni & 1) * 2];
                    const uint32_t* blp = &bl[ni >> 1][(ni & 1) * 2];
                    mma_f16(acc[mi][ni], ah[mi], bhp);
                    mma_f16(acc[mi][ni], ah[mi], blp);
                }
            }
        }
        __syncthreads();
        buf++; if (buf == 3) buf = 0;
    }

    int tb = n0 / HW;
    int hw0 = n0 - tb * HW;
#pragma unroll
    for (int mi = 0; mi < 4; mi++){
        int mrow = m0 + wm * 64 + mi * 16 + (lane >> 2);
        float b0 = bias ? __ldg(bias + mrow)     : 0.f;
        float b1 = bias ? __ldg(bias + mrow + 8) : 0.f;
#pragma unroll
        for (int ni = 0; ni < 4; ni++){
            int col = hw0 + wn * 32 + ni * 8 + (lane & 3) * 2;
            float2 v0 = make_float2(acc[mi][ni][0] + b0, acc[mi][ni][1] + b0);
            float2 v1 = make_float2(acc[mi][ni][2] + b1, acc[mi][ni][3] + b1);
            *(float2*)&out[((size_t)(tb * M + mrow)) * HW + col]     = v0;
            *(float2*)&out[((size_t)(tb * M + mrow + 8)) * HW + col] = v1;
        }
    }
}

// ---------------- classifier: [B,512,HW] -> [B,21,HW] ----------------
__global__ __launch_bounds__(256) void cls_kernel(
    const float* __restrict__ h, const float* __restrict__ w,
    const float* __restrict__ bias, float* __restrict__ out)
{
    __shared__ float ws[NCLS * OCH];
    int tid = threadIdx.x;
    for (int i = tid; i < NCLS * OCH; i += 256) ws[i] = w[i];
    __syncthreads();
    int n = blockIdx.x * 256 + tid;
    int b = n / HW, hw = n - b * HW;
    float acc[NCLS];
#pragma unroll
    for (int m = 0; m < NCLS; m++) acc[m] = bias[m];
    const float* hp = h + (size_t)b * OCH * HW + hw;
    for (int k = 0; k < OCH; k++){
        float v = hp[(size_t)k * HW];
#pragma unroll
        for (int m = 0; m < NCLS; m++)
            acc[m] = fmaf(v, ws[m * OCH + k], acc[m]);
    }
#pragma unroll
    for (int m = 0; m < NCLS; m++)
        out[((size_t)(b * NCLS + m)) * HW + hw] = acc[m];
}

// ---------------- BatchNorm ----------------
__global__ void bn_stats_kernel(const float* __restrict__ x,
                                const float* __restrict__ g,
                                const float* __restrict__ bta,
                                float* __restrict__ stats, int C)
{
    int c = blockIdx.x, tid = threadIdx.x;
    float s = 0.f, sq = 0.f;
    for (int i = tid; i < NB * HW; i += 256){
        int bb = i / HW;
        float v = x[((size_t)(bb * C + c)) * HW + (i - bb * HW)];
        s += v; sq += v * v;
    }
    __shared__ float sh1[256], sh2[256];
    sh1[tid] = s; sh2[tid] = sq;
    __syncthreads();
    for (int st = 128; st; st >>= 1){
        if (tid < st){ sh1[tid] += sh1[tid + st]; sh2[tid] += sh2[tid + st]; }
        __syncthreads();
    }
    if (tid == 0){
        float n = (float)(NB * HW);
        float m = sh1[0] / n;
        float var = sh2[0] / n - m * m;
        float sc = g[c] * rsqrtf(var + 1e-5f);
        stats[2 * c] = sc;
        stats[2 * c + 1] = bta[c] - m * sc;
    }
}

__global__ void bn_apply_kernel(const float* __restrict__ x,
                                const float* __restrict__ stats,
                                float* __restrict__ y, int C, int total)
{
    int i = blockIdx.x * 256 + threadIdx.x;
    if (i < total){
        int c = (i / HW) % C;
        y[i] = fmaxf(fmaf(x[i], stats[2 * c], stats[2 * c + 1]), 0.f);
    }
}

// ---------------- criss-cross attention ----------------
__global__ void cc_logits_col_kernel(const float* __restrict__ qkv,
                                     float* __restrict__ att)
{
    int w = blockIdx.x, b = blockIdx.y, tid = threadIdx.x;
    __shared__ float qs[32][48], ks[32][48];
    for (int i = tid; i < 32 * 48; i += 256){
        int c = i / 48, h = i - (i / 48) * 48;
        qs[c][h] = qkv[((size_t)((b * QKVC + c) * 48 + h)) * 48 + w];
        ks[c][h] = qkv[((size_t)((b * QKVC + 32 + c) * 48 + h)) * 48 + w];
    }
    __syncthreads();
    for (int i = tid; i < 48 * 48; i += 256){
        int h = i / 48, g = i - (i / 48) * 48;
        float s;
        if (g == h) s = NEG_INF;
        else {
            s = 0.f;
#pragma unroll
            for (int c = 0; c < 32; c++) s += qs[c][h] * ks[c][g];
        }
        att[((size_t)((b * 48 + h) * 48 + w)) * 96 + g] = s;
    }
}

__global__ void cc_logits_row_kernel(const float* __restrict__ qkv,
                                     float* __restrict__ att)
{
    int h = blockIdx.x, b = blockIdx.y, tid = threadIdx.x;
    __shared__ float qs[32][48], ks[32][48];
    for (int i = tid; i < 32 * 48; i += 256){
        int c = i / 48, w = i - (i / 48) * 48;
        qs[c][w] = qkv[((size_t)((b * QKVC + c) * 48 + h)) * 48 + w];
        ks[c][w] = qkv[((size_t)((b * QKVC + 32 + c) * 48 + h)) * 48 + w];
    }
    __syncthreads();
    for (int i = tid; i < 48 * 48; i += 256){
        int w = i / 48, v2 = i - (i / 48) * 48;
        float s = 0.f;
#pragma unroll
        for (int c = 0; c < 32; c++) s += qs[c][w] * ks[c][v2];
        att[((size_t)((b * 48 + h) * 48 + w)) * 96 + 48 + v2] = s;
    }
}

__global__ void cc_softmax_kernel(float* __restrict__ att)
{
    int row  = blockIdx.x * 8 + (threadIdx.x >> 5);
    int lane = threadIdx.x & 31;
    float* p = att + (size_t)row * 96;
    float v0 = p[lane], v1 = p[lane + 32], v2 = p[lane + 64];
    float mx = fmaxf(v0, fmaxf(v1, v2));
#pragma unroll
    for (int off = 16; off; off >>= 1) mx = fmaxf(mx, __shfl_xor_sync(0xffffffff, mx, off));
    float e0 = expf(v0 - mx), e1 = expf(v1 - mx), e2 = expf(v2 - mx);
    float s = e0 + e1 + e2;
#pragma unroll
    for (int off = 16; off; off >>= 1) s += __shfl_xor_sync(0xffffffff, s, off);
    float inv = 1.f / s;
    p[lane] = e0 * inv; p[lane + 32] = e1 * inv; p[lane + 64] = e2 * inv;
}

#define CC_SMEM ((256*48 + 48*48) * 4)

__global__ void cc_out_col_kernel(const float* __restrict__ qkv,
                                  const float* __restrict__ att,
                                  const float* __restrict__ xin,
                                  const float* __restrict__ gamma,
                                  float* __restrict__ out)
{
    extern __shared__ float cs[];
    float* vs = cs; float* as = cs + 256 * 48;
    int w = blockIdx.x, b = blockIdx.y, tid = threadIdx.x;
    for (int i = tid; i < 256 * 48; i += 256){
        int c = i / 48, g = i - (i / 48) * 48;
        vs[i] = qkv[((size_t)((b * QKVC + 64 + c) * 48 + g)) * 48 + w];
    }
    for (int i = tid; i < 48 * 48; i += 256){
        int h = i / 48, g = i - (i / 48) * 48;
        as[i] = att[((size_t)((b * 48 + h) * 48 + w)) * 96 + g];
    }
    __syncthreads();
    float gm = gamma[0];
    for (int i = tid; i < 256 * 48; i += 256){
        int c = i / 48, h = i - (i / 48) * 48;
        float s = 0.f;
#pragma unroll
        for (int g = 0; g < 48; g++) s += vs[c * 48 + g] * as[h * 48 + g];
        size_t o = ((size_t)((b * 256 + c) * 48 + h)) * 48 + w;
        out[o] = xin[o] + gm * s;
    }
}

__global__ void cc_out_row_kernel(const float* __restrict__ qkv,
                                  const float* __restrict__ att,
                                  const float* __restrict__ gamma,
                                  float* __restrict__ out)
{
    extern __shared__ float cs[];
    float* vs = cs; float* as = cs + 256 * 48;
    int h = blockIdx.x, b = blockIdx.y, tid = threadIdx.x;
    for (int i = tid; i < 256 * 48; i += 256){
        vs[i] = qkv[((size_t)(b * QKVC + 64 + i / 48) * 48 + h) * 48 + (i % 48)];
    }
    for (int i = tid; i < 48 * 48; i += 256){
        int w2 = i / 48, v2 = i - (i / 48) * 48;
        as[i] = att[((size_t)((b * 48 + h) * 48 + w2)) * 96 + 48 + v2];
    }
    __syncthreads();
    float gm = gamma[0];
    for (int i = tid; i < 256 * 48; i += 256){
        int c = i / 48, w2 = i - (i / 48) * 48;
        float s = 0.f;
#pragma unroll
        for (int v2 = 0; v2 < 48; v2++) s += vs[c * 48 + v2] * as[w2 * 48 + v2];
        size_t o = ((size_t)((b * 256 + c) * 48 + h)) * 48 + w2;
        out[o] += gm * s;
    }
}

// ---------------- grid attention ----------------
__global__ void gram_kernel(const float* __restrict__ qkv,
                            float* __restrict__ S)
{
    int b1 = blockIdx.x >> 4, b2 = blockIdx.x & 15;
    const float* qp = qkv + (size_t)b1 * (QKVC * HW);
    const float* kp = qkv + (size_t)b2 * (QKVC * HW) + 32 * HW;
    int tid = threadIdx.x;
    float s = 0.f;
    for (int i = tid; i < C8 * HW; i += 256) s += qp[i] * kp[i];
    __shared__ float sh[256];
    sh[tid] = s;
    __syncthreads();
    for (int st = 128; st; st >>= 1){
        if (tid < st) sh[tid] += sh[tid + st];
        __syncthreads();
    }
    if (tid == 0) S[blockIdx.x] = sh[0];
}

__global__ void myw_kernel(const float* __restrict__ S, float* __restrict__ Wm)
{
    int b1 = threadIdx.x;
    if (b1 < 16){
        int gh = b1 >> 2, gw = b1 & 3;
        float l[8];
        for (int j = 0; j < 4; j++){
            int b2 = j * 4 + gw;
            l[j] = (j == gh) ? NEG_INF : S[b1 * 16 + b2];
        }
        for (int j = 0; j < 4; j++) l[4 + j] = S[b1 * 16 + gh * 4 + j];
        float mx = NEG_INF;
        for (int j = 0; j < 8; j++) mx = fmaxf(mx, l[j]);
        float sm = 0.f;
        for (int j = 0; j < 8; j++){ l[j] = expf(l[j] - mx); sm += l[j]; }
        float inv = 1.f / sm;
        float w[16];
        for (int i = 0; i < 16; i++) w[i] = 0.f;
        for (int j = 0; j < 4; j++) w[j * 4 + gw] += l[j] * inv;
        for (int j = 0; j < 4; j++) w[gh * 4 + j] += l[4 + j] * inv;
        for (int i = 0; i < 16; i++) Wm[b1 * 16 + i] = w[i];
    }
}

__global__ void my_combine_kernel(const float* __restrict__ qkv,
                                  const float* __restrict__ Wm,
                                  const float* __restrict__ xin,
                                  const float* __restrict__ gamma,
                                  float* __restrict__ out)
{
    __shared__ float ws[256];
    if (threadIdx.x < 256) ws[threadIdx.x] = Wm[threadIdx.x];
    __syncthreads();
    const int PB = CMID * HW;
    int n = blockIdx.x * 256 + threadIdx.x;
    if (n < PB){
        float vv[16];
#pragma unroll
        for (int b = 0; b < 16; b++)
            vv[b] = qkv[(size_t)b * (QKVC * HW) + 64 * HW + n];
        float gm = gamma[0];
#pragma unroll
        for (int b1 = 0; b1 < 16; b1++){
            float o = 0.f;
#pragma unroll
            for (int b2 = 0; b2 < 16; b2++) o += ws[b1 * 16 + b2] * vv[b2];
            out[(size_t)b1 * PB + n] = gm * o + xin[(size_t)b1 * PB + n];
        }
    }
}

// ---------------- host ----------------
extern "C" void kernel_launch(void* const* d_in, const int* in_sizes, int n_in,
                              void* d_out, int out_size)
{
    const float* x      = (const float*)d_in[0];
    const float* w_a    = (const float*)d_in[1];
    const float* g_a    = (const float*)d_in[2];
    const float* b_a    = (const float*)d_in[3];
    const float* ccq_w  = (const float*)d_in[4];
    const float* ccq_b  = (const float*)d_in[5];
    const float* cck_w  = (const float*)d_in[6];
    const float* cck_b  = (const float*)d_in[7];
    const float* ccv_w  = (const float*)d_in[8];
    const float* ccv_b  = (const float*)d_in[9];
    const float* cc_gm  = (const float*)d_in[10];
    const float* w_b    = (const float*)d_in[11];
    const float* g_b    = (const float*)d_in[12];
    const float* b_b    = (const float*)d_in[13];
    const float* w_m1   = (const float*)d_in[14];
    const float* g_m1   = (const float*)d_in[15];
    const float* b_m1   = (const float*)d_in[16];
    const float* myq_w  = (const float*)d_in[17];
    const float* myq_b  = (const float*)d_in[18];
    const float* myk_w  = (const float*)d_in[19];
    const float* myk_b  = (const float*)d_in[20];
    const float* myv_w  = (const float*)d_in[21];
    const float* myv_b  = (const float*)d_in[22];
    const float* my_gm  = (const float*)d_in[23];
    const float* w_m2   = (const float*)d_in[24];
    const float* g_m2   = (const float*)d_in[25];
    const float* b_m2   = (const float*)d_in[26];
    const float* w_c    = (const float*)d_in[27];
    const float* g_c    = (const float*)d_in[28];
    const float* b_c    = (const float*)d_in[29];
    const float* w_cls  = (const float*)d_in[30];
    const float* b_cls  = (const float*)d_in[31];

    cudaFuncSetAttribute(mma_conv_kernel, cudaFuncAttributeMaxDynamicSharedMemorySize, MC_SMEM);
    cudaFuncSetAttribute(cc_out_col_kernel, cudaFuncAttributeMaxDynamicSharedMemorySize, CC_SMEM);
    cudaFuncSetAttribute(cc_out_row_kernel, cudaFuncAttributeMaxDynamicSharedMemorySize, CC_SMEM);

    float *pt0, *pcc, *pmy, *pt1, *pqkv, *ph, *pst, *pS, *pWm, *patt, *pBcc, *pBmy;
    cudaGetSymbolAddress((void**)&pt0, g_t0);
    cudaGetSymbolAddress((void**)&pcc, g_cc);
    cudaGetSymbolAddress((void**)&pmy, g_my);
    cudaGetSymbolAddress((void**)&pt1, g_t1);
    cudaGetSymbolAddress((void**)&pqkv, g_qkv);
    cudaGetSymbolAddress((void**)&ph,  g_h);
    cudaGetSymbolAddress((void**)&pst, g_stats);
    cudaGetSymbolAddress((void**)&pS,  g_S);
    cudaGetSymbolAddress((void**)&pWm, g_Wm);
    cudaGetSymbolAddress((void**)&patt, g_att);
    cudaGetSymbolAddress((void**)&pBcc, g_Bcc);
    cudaGetSymbolAddress((void**)&pBmy, g_Bmy);

    __half *XCh,*XCl,*ACTh,*ACTl;
    __half *WA,*WM1,*WB,*WM2,*WC,*WQcc,*WQmy;
    cudaGetSymbolAddress((void**)&XCh, g_XCh);   cudaGetSymbolAddress((void**)&XCl, g_XCl);
    cudaGetSymbolAddress((void**)&ACTh, g_ACTh); cudaGetSymbolAddress((void**)&ACTl, g_ACTl);
    cudaGetSymbolAddress((void**)&WA, g_WA);
    cudaGetSymbolAddress((void**)&WM1, g_WM1);
    cudaGetSymbolAddress((void**)&WB, g_WB);
    cudaGetSymbolAddress((void**)&WM2, g_WM2);
    cudaGetSymbolAddress((void**)&WC, g_WC);
    cudaGetSymbolAddress((void**)&WQcc, g_WQcc);
    cudaGetSymbolAddress((void**)&WQmy, g_WQmy);

    const dim3 blk(256);
    const dim3 tr_blk(32, 8);
    const int NT = NTOT / 128;
    const int TOT_MID = NB*CMID*HW;

    // weight prep
    wprep_kernel<<<(256*9216 + 255)/256, blk>>>(w_a,  WA,  256, 1024, 9);
    wprep_kernel<<<(256*9216 + 255)/256, blk>>>(w_m1, WM1, 256, 1024, 9);
    wprep_kernel<<<(256*2304 + 255)/256, blk>>>(w_b,  WB,  256, 256, 9);
    wprep_kernel<<<(256*2304 + 255)/256, blk>>>(w_m2, WM2, 256, 256, 9);
    wprep_kernel<<<(512*13824 + 255)/256, blk>>>(w_c, WC,  512, 1536, 9);
    wprep_qkv_kernel<<<(QKVC*256 + 255)/256, blk>>>(ccq_w, ccq_b, cck_w, cck_b, ccv_w, ccv_b,
                                                    WQcc, pBcc);
    wprep_qkv_kernel<<<(QKVC*256 + 255)/256, blk>>>(myq_w, myq_b, myk_w, myk_b, myv_w, myv_b,
                                                    WQmy, pBmy);

    // x -> XC[0:1024]
    to_nhwc_kernel<<<dim3(HW/32, 1024/32, NB), tr_blk>>>(x, XCh, XCl, 1024, 1536, 0);

    // conv_a, conv_m1
    mma_conv_kernel<<<dim3(NT, 2), blk, MC_SMEM>>>(WA, XCh, XCl, 256, 1024, 9, 1536, 0, nullptr, pt0);
    bn_stats_kernel<<<CMID, blk>>>(pt0, g_a, b_a, pst, CMID);
    bn_apply_kernel<<<(TOT_MID + 255)/256, blk>>>(pt0, pst, pcc, CMID, TOT_MID);

    mma_conv_kernel<<<dim3(NT, 2), blk, MC_SMEM>>>(WM1, XCh, XCl, 256, 1024, 9, 1536, 0, nullptr, pt0);
    bn_stats_kernel<<<CMID, blk>>>(pt0, g_m1, b_m1, pst, CMID);
    bn_apply_kernel<<<(TOT_MID + 255)/256, blk>>>(pt0, pst, pmy, CMID, TOT_MID);

    // cc attention x2
    {
        float* ca = pcc; float* cb = pt1;
        for (int it = 0; it < 2; it++){
            to_nhwc_kernel<<<dim3(HW/32, 256/32, NB), tr_blk>>>(ca, ACTh, ACTl, 256, 256, 0);
            mma_conv_kernel<<<dim3(NT, 3), blk, MC_SMEM>>>(WQcc, ACTh, ACTl,
                                                           QKVC, 256, 1, 256, 0, pBcc, pqkv);
            cc_logits_col_kernel<<<dim3(WW, NB), blk>>>(pqkv, patt);
            cc_logits_row_kernel<<<dim3(HH, NB), blk>>>(pqkv, patt);
            cc_softmax_kernel<<<NTOT/8, blk>>>(patt);
            cc_out_col_kernel<<<dim3(WW, NB), blk, CC_SMEM>>>(pqkv, patt, ca, cc_gm, cb);
            cc_out_row_kernel<<<dim3(HH, NB), blk, CC_SMEM>>>(pqkv, patt, cc_gm, cb);
            float* tmp = ca; ca = cb; cb = tmp;
        }
    }

    // my attention x2
    {
        float* ma = pmy; float* mb = pt1;
        for (int it = 0; it < 2; it++){
            to_nhwc_kernel<<<dim3(HW/32, 256/32, NB), tr_blk>>>(ma, ACTh, ACTl, 256, 256, 0);
            mma_conv_kernel<<<dim3(NT, 3), blk, MC_SMEM>>>(WQmy, ACTh, ACTl,
                                                           QKVC, 256, 1, 256, 0, pBmy, pqkv);
            gram_kernel<<<256, blk>>>(pqkv, pS);
            myw_kernel<<<1, 32>>>(pS, pWm);
            my_combine_kernel<<<(CMID*HW + 255)/256, blk>>>(pqkv, pWm, ma, my_gm, mb);
            float* tmp = ma; ma = mb; mb = tmp;
        }
    }

    // conv_b: input pcc -> BN -> XC@1024 (fused)
    to_nhwc_kernel<<<dim3(HW/32, 256/32, NB), tr_blk>>>(pcc, ACTh, ACTl, 256, 256, 0);
    mma_conv_kernel<<<dim3(NT, 2), blk, MC_SMEM>>>(WB, ACTh, ACTl, 256, 256, 9, 256, 0, nullptr, pt0);
    bn_stats_kernel<<<CMID, blk>>>(pt0, g_b, b_b, pst, CMID);
    bn_to_nhwc_kernel<<<dim3(HW/32, 256/32, NB), tr_blk>>>(pt0, pst, XCh, XCl, 256, 1536, 1024);

    // conv_m2: input pmy -> BN -> XC@1280 (fused)
    to_nhwc_kernel<<<dim3(HW/32, 256/32, NB), tr_blk>>>(pmy, ACTh, ACTl, 256, 256, 0);
    mma_conv_kernel<<<dim3(NT, 2), blk, MC_SMEM>>>(WM2, ACTh, ACTl, 256, 256, 9, 256, 0, nullptr, pt0);
    bn_stats_kernel<<<CMID, blk>>>(pt0, g_m2, b_m2, pst, CMID);
    bn_to_nhwc_kernel<<<dim3(HW/32, 256/32, NB), tr_blk>>>(pt0, pst, XCh, XCl, 256, 1536, 1280);

    // conv_c + BN
    mma_conv_kernel<<<dim3(NT, 4), blk, MC_SMEM>>>(WC, XCh, XCl, 512, 1536, 9, 1536, 0, nullptr, ph);
    bn_stats_kernel<<<OCH, blk>>>(ph, g_c, b_c, pst, OCH);
    bn_apply_kernel<<<(NB*OCH*HW + 255)/256, blk>>>(ph, pst, ph, OCH, NB*OCH*HW);

    // classifier (dedicated slim kernel)
    cls_kernel<<<NTOT/256, blk>>>(ph, w_cls, b_cls, (float*)d_out);
}

// round 15
// speedup vs baseline: 1.3416x; 1.0880x over previous
#include <cuda_runtime.h>
#include <cuda_fp16.h>
#include <math.h>
#include <stdint.h>

#define NB   16
#define CIN  1024
#define CMID 256
#define C8   32
#define HH   48
#define WW   48
#define HW   (HH*WW)
#define NTOT (NB*HW)
#define OCH  512
#define NCLS 21
#define QKVC 384
#define NEG_INF (__int_as_float(0xff800000))

// ---------------- static scratch ----------------
__device__ float g_t0[NB*CMID*HW];
__device__ float g_cc[NB*CMID*HW];
__device__ float g_my[NB*CMID*HW];
__device__ float g_t1[NB*CMID*HW];
__device__ float g_qkv[(size_t)NB*QKVC*HW];
__device__ float g_h [NB*OCH*HW];
__device__ float g_stats[2*OCH];
__device__ float g_S[256];
__device__ float g_Wm[256];
__device__ float g_att[(size_t)NTOT*96];
__device__ float g_Bcc[QKVC];
__device__ float g_Bmy[QKVC];

__device__ __align__(256) __half g_XCh[(size_t)NTOT*1536];
__device__ __align__(256) __half g_XCl[(size_t)NTOT*1536];
__device__ __align__(256) __half g_ACTh[(size_t)NTOT*256];
__device__ __align__(256) __half g_ACTl[(size_t)NTOT*256];
__device__ __align__(256) __half g_WA [256*9216];
__device__ __align__(256) __half g_WM1[256*9216];
__device__ __align__(256) __half g_WB [256*2304];
__device__ __align__(256) __half g_WM2[256*2304];
__device__ __align__(256) __half g_WC [512*13824];
__device__ __align__(256) __half g_WQcc[QKVC*256];
__device__ __align__(256) __half g_WQmy[QKVC*256];

// ---------------- helpers ----------------
__device__ __forceinline__ uint32_t smem_u32(const void* p){
    uint32_t a;
    asm("{ .reg .u64 t; cvta.to.shared.u64 t, %1; cvt.u32.u64 %0, t; }" : "=r"(a) : "l"(p));
    return a;
}
__device__ __forceinline__ void cp16(uint32_t s, const void* g, uint32_t sz){
    asm volatile("cp.async.cg.shared.global [%0], [%1], 16, %2;" :: "r"(s), "l"(g), "r"(sz) : "memory");
}
__device__ __forceinline__ void ldmx4(uint32_t* r, uint32_t a){
    asm volatile("ldmatrix.sync.aligned.m8n8.x4.shared.b16 {%0,%1,%2,%3}, [%4];"
        : "=r"(r[0]),"=r"(r[1]),"=r"(r[2]),"=r"(r[3]) : "r"(a));
}
__device__ __forceinline__ void mma_f16(float* d, const uint32_t* a, const uint32_t* b){
    asm volatile("mma.sync.aligned.m16n8k16.row.col.f32.f16.f16.f32 "
        "{%0,%1,%2,%3}, {%4,%5,%6,%7}, {%8,%9}, {%0,%1,%2,%3};"
        : "+f"(d[0]),"+f"(d[1]),"+f"(d[2]),"+f"(d[3])
        : "r"(a[0]),"r"(a[1]),"r"(a[2]),"r"(a[3]), "r"(b[0]),"r"(b[1]));
}

// ---------------- NCHW fp32 -> NHWC fp16 hi/lo ----------------
__global__ void to_nhwc_kernel(const float* __restrict__ src,
                               __half* __restrict__ hi,
                               __half* __restrict__ lo,
                               int C, int RS, int co)
{
    __shared__ float t[32][33];
    int hw0 = blockIdx.x * 32, c0 = blockIdx.y * 32, b = blockIdx.z;
    int lx = threadIdx.x, ly = threadIdx.y;
    for (int i = ly; i < 32; i += 8)
        t[i][lx] = src[((size_t)(b * C + c0 + i)) * HW + hw0 + lx];
    __syncthreads();
    for (int i = ly; i < 32; i += 8){
        float v = t[lx][i];
        __half h = __float2half_rn(v);
        size_t o = ((size_t)(b * HW + hw0 + i)) * RS + co + c0 + lx;
        hi[o] = h;
        lo[o] = __float2half_rn(v - __half2float(h));
    }
}

__global__ void bn_to_nhwc_kernel(const float* __restrict__ src,
                                  const float* __restrict__ stats,
                                  __half* __restrict__ hi,
                                  __half* __restrict__ lo,
                                  int C, int RS, int co)
{
    __shared__ float t[32][33];
    int hw0 = blockIdx.x * 32, c0 = blockIdx.y * 32, b = blockIdx.z;
    int lx = threadIdx.x, ly = threadIdx.y;
    for (int i = ly; i < 32; i += 8){
        int c = c0 + i;
        float v = src[((size_t)(b * C + c)) * HW + hw0 + lx];
        t[i][lx] = fmaxf(fmaf(v, stats[2*c], stats[2*c+1]), 0.f);
    }
    __syncthreads();
    for (int i = ly; i < 32; i += 8){
        float v = t[lx][i];
        __half h = __float2half_rn(v);
        size_t o = ((size_t)(b * HW + hw0 + i)) * RS + co + c0 + lx;
        hi[o] = h;
        lo[o] = __float2half_rn(v - __half2float(h));
    }
}

// ---------------- weight prep (fp16 hi only) ----------------
__global__ void wprep_kernel(const float* __restrict__ w,
                             __half* __restrict__ hi,
                             int M, int C, int ntaps)
{
    int i = blockIdx.x * 256 + threadIdx.x;
    int Kt = ntaps * C;
    if (i < M * Kt){
        int m = i / Kt; int rest = i - m * Kt; int t = rest / C; int c = rest - t * C;
        hi[i] = __float2half_rn(w[(size_t)(m * C + c) * ntaps + t]);
    }
}

__global__ void wprep_qkv_kernel(const float* __restrict__ qw, const float* __restrict__ qb,
                                 const float* __restrict__ kw, const float* __restrict__ kb,
                                 const float* __restrict__ vw, const float* __restrict__ vb,
                                 __half* __restrict__ hi,
                                 float* __restrict__ bias)
{
    int i = blockIdx.x * 256 + threadIdx.x;
    if (i < QKVC * 256){
        int m = i >> 8, c = i & 255;
        float v = 0.f;
        if (m < 32)       v = qw[m * 256 + c];
        else if (m < 64)  v = kw[(m - 32) * 256 + c];
        else if (m < 320) v = vw[(m - 64) * 256 + c];
        hi[i] = __float2half_rn(v);
    }
    if (i < QKVC){
        float bv = 0.f;
        if (i < 32)       bv = qb[i];
        else if (i < 64)  bv = kb[i - 32];
        else if (i < 320) bv = vb[i - 64];
        bias[i] = bv;
    }
}

// ---------------- mma.sync implicit-GEMM conv (fp16 2-product, 2-stage) -------
#define MC_BUF  30720
#define MC_SMEM (2*MC_BUF)   // 61440 -> 2+ CTAs/SM

struct McCtx {
    const __half *A, *Bh, *Bl;
    int C, ntaps, Ktot, cpT, RS, co;
    int r, half, b, yy, xx, am;
    uint32_t sb;
};

__device__ __forceinline__ void mc_load(const McCtx& cx, int cc, int buf)
{
    int t   = cc / cx.cpT;
    int ci0 = (cc - t * cx.cpT) << 5;
    uint32_t dst = cx.sb + buf * MC_BUF + cx.r * 80 + cx.half * 32;
    {
        size_t off = (size_t)cx.am * cx.Ktot + t * cx.C + ci0 + cx.half * 16;
        cp16(dst,      cx.A + off,     16);
        cp16(dst + 16, cx.A + off + 8, 16);
    }
    {
        int dy = 0, dx = 0;
        if (cx.ntaps == 9){ dy = t / 3 - 1; dx = t - (t / 3) * 3 - 1; }
        int ys = cx.yy + dy, xs = cx.xx + dx;
        bool bv = (ys >= 0 && ys < HH && xs >= 0 && xs < WW);
        size_t off = bv ? ((size_t)(cx.b * HW + ys * WW + xs) * cx.RS + cx.co + ci0 + cx.half * 16) : 0;
        uint32_t sz = bv ? 16u : 0u;
        cp16(dst + 10240,      cx.Bh + off,     sz);
        cp16(dst + 10240 + 16, cx.Bh + off + 8, sz);
        cp16(dst + 20480,      cx.Bl + off,     sz);
        cp16(dst + 20480 + 16, cx.Bl + off + 8, sz);
    }
}

__global__ __launch_bounds__(256) void mma_conv_kernel(
    const __half* __restrict__ A,
    const __half* __restrict__ Bh, const __half* __restrict__ Bl,
    int M, int C, int ntaps, int RS, int co,
    const float* __restrict__ bias,
    float* __restrict__ out)
{
    extern __shared__ char dynsm[];
    const int tid = threadIdx.x, lane = tid & 31, wid = tid >> 5;
    const int wm = wid & 1, wn = wid >> 1;
    const int m0 = blockIdx.y * 128;
    const int n0 = blockIdx.x * 128;

    McCtx cx;
    cx.A = A; cx.Bh = Bh; cx.Bl = Bl;
    cx.C = C; cx.ntaps = ntaps; cx.Ktot = ntaps * C; cx.cpT = C >> 5;
    cx.RS = RS; cx.co = co;
    cx.r = tid >> 1; cx.half = tid & 1;
    {
        int n = n0 + cx.r;
        cx.b = n / HW;
        int hw = n - cx.b * HW;
        cx.yy = hw / WW;
        cx.xx = hw - cx.yy * WW;
    }
    cx.am = m0 + cx.r;
    cx.sb = smem_u32(dynsm);

    float acc[4][4][4];
#pragma unroll
    for (int i = 0; i < 4; i++)
#pragma unroll
        for (int j = 0; j < 4; j++)
#pragma unroll
            for (int q = 0; q < 4; q++) acc[i][j][q] = 0.f;

    const int NC = cx.Ktot >> 5;

    mc_load(cx, 0, 0);
    asm volatile("cp.async.commit_group;" ::: "memory");

    const uint32_t aRowOff = (uint32_t)(lane & 15) * 80;
    const uint32_t aColOff = (uint32_t)(lane >> 4) * 16;
    const uint32_t bRowOff = (uint32_t)((lane & 7) + ((lane >> 4) << 3)) * 80;
    const uint32_t bColOff = (uint32_t)((lane >> 3) & 1) * 16;

    for (int cc = 0; cc < NC; cc++){
        int buf = cc & 1;
        if (cc + 1 < NC){
            mc_load(cx, cc + 1, (cc + 1) & 1);
            asm volatile("cp.async.commit_group;" ::: "memory");
            asm volatile("cp.async.wait_group 1;" ::: "memory");
        } else {
            asm volatile("cp.async.wait_group 0;" ::: "memory");
        }
        __syncthreads();
        uint32_t base = cx.sb + buf * MC_BUF;
#pragma unroll
        for (int k16 = 0; k16 < 2; k16++){
            uint32_t ac = (uint32_t)k16 * 32 + aColOff;
            uint32_t bc = (uint32_t)k16 * 32 + bColOff;
            uint32_t ah[4][4], bh[2][4], bl[2][4];
#pragma unroll
            for (int mi = 0; mi < 4; mi++){
                uint32_t ad = base + (uint32_t)(wm * 64 + mi * 16) * 80 + aRowOff + ac;
                ldmx4(ah[mi], ad);
            }
#pragma unroll
            for (int ng = 0; ng < 2; ng++){
                uint32_t bd = base + 10240 + (uint32_t)(wn * 32 + ng * 16) * 80 + bRowOff + bc;
                ldmx4(bh[ng], bd);
                ldmx4(bl[ng], bd + 10240);
            }
#pragma unroll
            for (int mi = 0; mi < 4; mi++){
#pragma unroll
                for (int ni = 0; ni < 4; ni++){
                    const uint32_t* bhp = &bh[ni >> 1][(ni & 1) * 2];
                    const uint32_t* blp = &bl[ni >> 1][(ni & 1) * 2];
                    mma_f16(acc[mi][ni], ah[mi], bhp);
                    mma_f16(acc[mi][ni], ah[mi], blp);
                }
            }
        }
        __syncthreads();
    }

    int tb = n0 / HW;
    int hw0 = n0 - tb * HW;
#pragma unroll
    for (int mi = 0; mi < 4; mi++){
        int mrow = m0 + wm * 64 + mi * 16 + (lane >> 2);
        float b0 = bias ? __ldg(bias + mrow)     : 0.f;
        float b1 = bias ? __ldg(bias + mrow + 8) : 0.f;
#pragma unroll
        for (int ni = 0; ni < 4; ni++){
            int col = hw0 + wn * 32 + ni * 8 + (lane & 3) * 2;
            float2 v0 = make_float2(acc[mi][ni][0] + b0, acc[mi][ni][1] + b0);
            float2 v1 = make_float2(acc[mi][ni][2] + b1, acc[mi][ni][3] + b1);
            *(float2*)&out[((size_t)(tb * M + mrow)) * HW + col]     = v0;
            *(float2*)&out[((size_t)(tb * M + mrow + 8)) * HW + col] = v1;
        }
    }
}

// ---------------- classifier: [B,512,HW] -> [B,21,HW] ----------------
__global__ __launch_bounds__(256) void cls_kernel(
    const float* __restrict__ h, const float* __restrict__ w,
    const float* __restrict__ bias, float* __restrict__ out)
{
    __shared__ float ws[NCLS * OCH];
    int tid = threadIdx.x;
    for (int i = tid; i < NCLS * OCH; i += 256) ws[i] = w[i];
    __syncthreads();
    int n = blockIdx.x * 256 + tid;
    int b = n / HW, hw = n - b * HW;
    float acc[NCLS];
#pragma unroll
    for (int m = 0; m < NCLS; m++) acc[m] = bias[m];
    const float* hp = h + (size_t)b * OCH * HW + hw;
    for (int k = 0; k < OCH; k++){
        float v = hp[(size_t)k * HW];
#pragma unroll
        for (int m = 0; m < NCLS; m++)
            acc[m] = fmaf(v, ws[m * OCH + k], acc[m]);
    }
#pragma unroll
    for (int m = 0; m < NCLS; m++)
        out[((size_t)(b * NCLS + m)) * HW + hw] = acc[m];
}

// ---------------- BatchNorm ----------------
__global__ void bn_stats_kernel(const float* __restrict__ x,
                                const float* __restrict__ g,
                                const float* __restrict__ bta,
                                float* __restrict__ stats, int C)
{
    int c = blockIdx.x, tid = threadIdx.x;
    float s = 0.f, sq = 0.f;
    for (int i = tid; i < NB * HW; i += 256){
        int bb = i / HW;
        float v = x[((size_t)(bb * C + c)) * HW + (i - bb * HW)];
        s += v; sq += v * v;
    }
    __shared__ float sh1[256], sh2[256];
    sh1[tid] = s; sh2[tid] = sq;
    __syncthreads();
    for (int st = 128; st; st >>= 1){
        if (tid < st){ sh1[tid] += sh1[tid + st]; sh2[tid] += sh2[tid + st]; }
        __syncthreads();
    }
    if (tid == 0){
        float n = (float)(NB * HW);
        float m = sh1[0] / n;
        float var = sh2[0] / n - m * m;
        float sc = g[c] * rsqrtf(var + 1e-5f);
        stats[2 * c] = sc;
        stats[2 * c + 1] = bta[c] - m * sc;
    }
}

__global__ void bn_apply_kernel(const float* __restrict__ x,
                                const float* __restrict__ stats,
                                float* __restrict__ y, int C, int total)
{
    int i = blockIdx.x * 256 + threadIdx.x;
    if (i < total){
        int c = (i / HW) % C;
        y[i] = fmaxf(fmaf(x[i], stats[2 * c], stats[2 * c + 1]), 0.f);
    }
}

// ---------------- criss-cross attention ----------------
__global__ void cc_logits_col_kernel(const float* __restrict__ qkv,
                                     float* __restrict__ att)
{
    int w = blockIdx.x, b = blockIdx.y, tid = threadIdx.x;
    __shared__ float qs[32][48], ks[32][48];
    for (int i = tid; i < 32 * 48; i += 256){
        int c = i / 48, h = i - (i / 48) * 48;
        qs[c][h] = qkv[((size_t)((b * QKVC + c) * 48 + h)) * 48 + w];
        ks[c][h] = qkv[((size_t)((b * QKVC + 32 + c) * 48 + h)) * 48 + w];
    }
    __syncthreads();
    for (int i = tid; i < 48 * 48; i += 256){
        int h = i / 48, g = i - (i / 48) * 48;
        float s;
        if (g == h) s = NEG_INF;
        else {
            s = 0.f;
#pragma unroll
            for (int c = 0; c < 32; c++) s += qs[c][h] * ks[c][g];
        }
        att[((size_t)((b * 48 + h) * 48 + w)) * 96 + g] = s;
    }
}

__global__ void cc_logits_row_kernel(const float* __restrict__ qkv,
                                     float* __restrict__ att)
{
    int h = blockIdx.x, b = blockIdx.y, tid = threadIdx.x;
    __shared__ float qs[32][48], ks[32][48];
    for (int i = tid; i < 32 * 48; i += 256){
        int c = i / 48, w = i - (i / 48) * 48;
        qs[c][w] = qkv[((size_t)((b * QKVC + c) * 48 + h)) * 48 + w];
        ks[c][w] = qkv[((size_t)((b * QKVC + 32 + c) * 48 + h)) * 48 + w];
    }
    __syncthreads();
    for (int i = tid; i < 48 * 48; i += 256){
        int w = i / 48, v2 = i - (i / 48) * 48;
        float s = 0.f;
#pragma unroll
        for (int c = 0; c < 32; c++) s += qs[c][w] * ks[c][v2];
        att[((size_t)((b * 48 + h) * 48 + w)) * 96 + 48 + v2] = s;
    }
}

__global__ void cc_softmax_kernel(float* __restrict__ att)
{
    int row  = blockIdx.x * 8 + (threadIdx.x >> 5);
    int lane = threadIdx.x & 31;
    float* p = att + (size_t)row * 96;
    float v0 = p[lane], v1 = p[lane + 32], v2 = p[lane + 64];
    float mx = fmaxf(v0, fmaxf(v1, v2));
#pragma unroll
    for (int off = 16; off; off >>= 1) mx = fmaxf(mx, __shfl_xor_sync(0xffffffff, mx, off));
    float e0 = expf(v0 - mx), e1 = expf(v1 - mx), e2 = expf(v2 - mx);
    float s = e0 + e1 + e2;
#pragma unroll
    for (int off = 16; off; off >>= 1) s += __shfl_xor_sync(0xffffffff, s, off);
    float inv = 1.f / s;
    p[lane] = e0 * inv; p[lane + 32] = e1 * inv; p[lane + 64] = e2 * inv;
}

#define CC_SMEM ((256*48 + 48*48) * 4)

__global__ void cc_out_col_kernel(const float* __restrict__ qkv,
                                  const float* __restrict__ att,
                                  const float* __restrict__ xin,
                                  const float* __restrict__ gamma,
                                  float* __restrict__ out)
{
    extern __shared__ float cs[];
    float* vs = cs; float* as = cs + 256 * 48;
    int w = blockIdx.x, b = blockIdx.y, tid = threadIdx.x;
    for (int i = tid; i < 256 * 48; i += 256){
        int c = i / 48, g = i - (i / 48) * 48;
        vs[i] = qkv[((size_t)((b * QKVC + 64 + c) * 48 + g)) * 48 + w];
    }
    for (int i = tid; i < 48 * 48; i += 256){
        int h = i / 48, g = i - (i / 48) * 48;
        as[i] = att[((size_t)((b * 48 + h) * 48 + w)) * 96 + g];
    }
    __syncthreads();
    float gm = gamma[0];
    for (int i = tid; i < 256 * 48; i += 256){
        int c = i / 48, h = i - (i / 48) * 48;
        float s = 0.f;
#pragma unroll
        for (int g = 0; g < 48; g++) s += vs[c * 48 + g] * as[h * 48 + g];
        size_t o = ((size_t)((b * 256 + c) * 48 + h)) * 48 + w;
        out[o] = xin[o] + gm * s;
    }
}

__global__ void cc_out_row_kernel(const float* __restrict__ qkv,
                                  const float* __restrict__ att,
                                  const float* __restrict__ gamma,
                                  float* __restrict__ out)
{
    extern __shared__ float cs[];
    float* vs = cs; float* as = cs + 256 * 48;
    int h = blockIdx.x, b = blockIdx.y, tid = threadIdx.x;
    for (int i = tid; i < 256 * 48; i += 256){
        vs[i] = qkv[((size_t)(b * QKVC + 64 + i / 48) * 48 + h) * 48 + (i % 48)];
    }
    for (int i = tid; i < 48 * 48; i += 256){
        int w2 = i / 48, v2 = i - (i / 48) * 48;
        as[i] = att[((size_t)((b * 48 + h) * 48 + w2)) * 96 + 48 + v2];
    }
    __syncthreads();
    float gm = gamma[0];
    for (int i = tid; i < 256 * 48; i += 256){
        int c = i / 48, w2 = i - (i / 48) * 48;
        float s = 0.f;
#pragma unroll
        for (int v2 = 0; v2 < 48; v2++) s += vs[c * 48 + v2] * as[w2 * 48 + v2];
        size_t o = ((size_t)((b * 256 + c) * 48 + h)) * 48 + w2;
        out[o] += gm * s;
    }
}

// ---------------- grid attention ----------------
__global__ void gram_kernel(const float* __restrict__ qkv,
                            float* __restrict__ S)
{
    int b1 = blockIdx.x >> 4, b2 = blockIdx.x & 15;
    const float* qp = qkv + (size_t)b1 * (QKVC * HW);
    const float* kp = qkv + (size_t)b2 * (QKVC * HW) + 32 * HW;
    int tid = threadIdx.x;
    float s = 0.f;
    for (int i = tid; i < C8 * HW; i += 256) s += qp[i] * kp[i];
    __shared__ float sh[256];
    sh[tid] = s;
    __syncthreads();
    for (int st = 128; st; st >>= 1){
        if (tid < st) sh[tid] += sh[tid + st];
        __syncthreads();
    }
    if (tid == 0) S[blockIdx.x] = sh[0];
}

__global__ void myw_kernel(const float* __restrict__ S, float* __restrict__ Wm)
{
    int b1 = threadIdx.x;
    if (b1 < 16){
        int gh = b1 >> 2, gw = b1 & 3;
        float l[8];
        for (int j = 0; j < 4; j++){
            int b2 = j * 4 + gw;
            l[j] = (j == gh) ? NEG_INF : S[b1 * 16 + b2];
        }
        for (int j = 0; j < 4; j++) l[4 + j] = S[b1 * 16 + gh * 4 + j];
        float mx = NEG_INF;
        for (int j = 0; j < 8; j++) mx = fmaxf(mx, l[j]);
        float sm = 0.f;
        for (int j = 0; j < 8; j++){ l[j] = expf(l[j] - mx); sm += l[j]; }
        float inv = 1.f / sm;
        float w[16];
        for (int i = 0; i < 16; i++) w[i] = 0.f;
        for (int j = 0; j < 4; j++) w[j * 4 + gw] += l[j] * inv;
        for (int j = 0; j < 4; j++) w[gh * 4 + j] += l[4 + j] * inv;
        for (int i = 0; i < 16; i++) Wm[b1 * 16 + i] = w[i];
    }
}

__global__ void my_combine_kernel(const float* __restrict__ qkv,
                                  const float* __restrict__ Wm,
                                  const float* __restrict__ xin,
                                  const float* __restrict__ gamma,
                                  float* __restrict__ out)
{
    __shared__ float ws[256];
    if (threadIdx.x < 256) ws[threadIdx.x] = Wm[threadIdx.x];
    __syncthreads();
    const int PB = CMID * HW;
    int n = blockIdx.x * 256 + threadIdx.x;
    if (n < PB){
        float vv[16];
#pragma unroll
        for (int b = 0; b < 16; b++)
            vv[b] = qkv[(size_t)b * (QKVC * HW) + 64 * HW + n];
        float gm = gamma[0];
#pragma unroll
        for (int b1 = 0; b1 < 16; b1++){
            float o = 0.f;
#pragma unroll
            for (int b2 = 0; b2 < 16; b2++) o += ws[b1 * 16 + b2] * vv[b2];
            out[(size_t)b1 * PB + n] = gm * o + xin[(size_t)b1 * PB + n];
        }
    }
}

// ---------------- host ----------------
extern "C" void kernel_launch(void* const* d_in, const int* in_sizes, int n_in,
                              void* d_out, int out_size)
{
    const float* x      = (const float*)d_in[0];
    const float* w_a    = (const float*)d_in[1];
    const float* g_a    = (const float*)d_in[2];
    const float* b_a    = (const float*)d_in[3];
    const float* ccq_w  = (const float*)d_in[4];
    const float* ccq_b  = (const float*)d_in[5];
    const float* cck_w  = (const float*)d_in[6];
    const float* cck_b  = (const float*)d_in[7];
    const float* ccv_w  = (const float*)d_in[8];
    const float* ccv_b  = (const float*)d_in[9];
    const float* cc_gm  = (const float*)d_in[10];
    const float* w_b    = (const float*)d_in[11];
    const float* g_b    = (const float*)d_in[12];
    const float* b_b    = (const float*)d_in[13];
    const float* w_m1   = (const float*)d_in[14];
    const float* g_m1   = (const float*)d_in[15];
    const float* b_m1   = (const float*)d_in[16];
    const float* myq_w  = (const float*)d_in[17];
    const float* myq_b  = (const float*)d_in[18];
    const float* myk_w  = (const float*)d_in[19];
    const float* myk_b  = (const float*)d_in[20];
    const float* myv_w  = (const float*)d_in[21];
    const float* myv_b  = (const float*)d_in[22];
    const float* my_gm  = (const float*)d_in[23];
    const float* w_m2   = (const float*)d_in[24];
    const float* g_m2   = (const float*)d_in[25];
    const float* b_m2   = (const float*)d_in[26];
    const float* w_c    = (const float*)d_in[27];
    const float* g_c    = (const float*)d_in[28];
    const float* b_c    = (const float*)d_in[29];
    const float* w_cls  = (const float*)d_in[30];
    const float* b_cls  = (const float*)d_in[31];

    cudaFuncSetAttribute(mma_conv_kernel, cudaFuncAttributeMaxDynamicSharedMemorySize, MC_SMEM);
    cudaFuncSetAttribute(cc_out_col_kernel, cudaFuncAttributeMaxDynamicSharedMemorySize, CC_SMEM);
    cudaFuncSetAttribute(cc_out_row_kernel, cudaFuncAttributeMaxDynamicSharedMemorySize, CC_SMEM);

    float *pt0, *pcc, *pmy, *pt1, *pqkv, *ph, *pst, *pS, *pWm, *patt, *pBcc, *pBmy;
    cudaGetSymbolAddress((void**)&pt0, g_t0);
    cudaGetSymbolAddress((void**)&pcc, g_cc);
    cudaGetSymbolAddress((void**)&pmy, g_my);
    cudaGetSymbolAddress((void**)&pt1, g_t1);
    cudaGetSymbolAddress((void**)&pqkv, g_qkv);
    cudaGetSymbolAddress((void**)&ph,  g_h);
    cudaGetSymbolAddress((void**)&pst, g_stats);
    cudaGetSymbolAddress((void**)&pS,  g_S);
    cudaGetSymbolAddress((void**)&pWm, g_Wm);
    cudaGetSymbolAddress((void**)&patt, g_att);
    cudaGetSymbolAddress((void**)&pBcc, g_Bcc);
    cudaGetSymbolAddress((void**)&pBmy, g_Bmy);

    __half *XCh,*XCl,*ACTh,*ACTl;
    __half *WA,*WM1,*WB,*WM2,*WC,*WQcc,*WQmy;
    cudaGetSymbolAddress((void**)&XCh, g_XCh);   cudaGetSymbolAddress((void**)&XCl, g_XCl);
    cudaGetSymbolAddress((void**)&ACTh, g_ACTh); cudaGetSymbolAddress((void**)&ACTl, g_ACTl);
    cudaGetSymbolAddress((void**)&WA, g_WA);
    cudaGetSymbolAddress((void**)&WM1, g_WM1);
    cudaGetSymbolAddress((void**)&WB, g_WB);
    cudaGetSymbolAddress((void**)&WM2, g_WM2);
    cudaGetSymbolAddress((void**)&WC, g_WC);
    cudaGetSymbolAddress((void**)&WQcc, g_WQcc);
    cudaGetSymbolAddress((void**)&WQmy, g_WQmy);

    const dim3 blk(256);
    const dim3 tr_blk(32, 8);
    const int NT = NTOT / 128;
    const int TOT_MID = NB*CMID*HW;

    // weight prep
    wprep_kernel<<<(256*9216 + 255)/256, blk>>>(w_a,  WA,  256, 1024, 9);
    wprep_kernel<<<(256*9216 + 255)/256, blk>>>(w_m1, WM1, 256, 1024, 9);
    wprep_kernel<<<(256*2304 + 255)/256, blk>>>(w_b,  WB,  256, 256, 9);
    wprep_kernel<<<(256*2304 + 255)/256, blk>>>(w_m2, WM2, 256, 256, 9);
    wprep_kernel<<<(512*13824 + 255)/256, blk>>>(w_c, WC,  512, 1536, 9);
    wprep_qkv_kernel<<<(QKVC*256 + 255)/256, blk>>>(ccq_w, ccq_b, cck_w, cck_b, ccv_w, ccv_b,
                                                    WQcc, pBcc);
    wprep_qkv_kernel<<<(QKVC*256 + 255)/256, blk>>>(myq_w, myq_b, myk_w, myk_b, myv_w, myv_b,
                                                    WQmy, pBmy);

    // x -> XC[0:1024]
    to_nhwc_kernel<<<dim3(HW/32, 1024/32, NB), tr_blk>>>(x, XCh, XCl, 1024, 1536, 0);

    // conv_a, conv_m1
    mma_conv_kernel<<<dim3(NT, 2), blk, MC_SMEM>>>(WA, XCh, XCl, 256, 1024, 9, 1536, 0, nullptr, pt0);
    bn_stats_kernel<<<CMID, blk>>>(pt0, g_a, b_a, pst, CMID);
    bn_apply_kernel<<<(TOT_MID + 255)/256, blk>>>(pt0, pst, pcc, CMID, TOT_MID);

    mma_conv_kernel<<<dim3(NT, 2), blk, MC_SMEM>>>(WM1, XCh, XCl, 256, 1024, 9, 1536, 0, nullptr, pt0);
    bn_stats_kernel<<<CMID, blk>>>(pt0, g_m1, b_m1, pst, CMID);
    bn_apply_kernel<<<(TOT_MID + 255)/256, blk>>>(pt0, pst, pmy, CMID, TOT_MID);

    // cc attention x2
    {
        float* ca = pcc; float* cb = pt1;
        for (int it = 0; it < 2; it++){
            to_nhwc_kernel<<<dim3(HW/32, 256/32, NB), tr_blk>>>(ca, ACTh, ACTl, 256, 256, 0);
            mma_conv_kernel<<<dim3(NT, 3), blk, MC_SMEM>>>(WQcc, ACTh, ACTl,
                                                           QKVC, 256, 1, 256, 0, pBcc, pqkv);
            cc_logits_col_kernel<<<dim3(WW, NB), blk>>>(pqkv, patt);
            cc_logits_row_kernel<<<dim3(HH, NB), blk>>>(pqkv, patt);
            cc_softmax_kernel<<<NTOT/8, blk>>>(patt);
            cc_out_col_kernel<<<dim3(WW, NB), blk, CC_SMEM>>>(pqkv, patt, ca, cc_gm, cb);
            cc_out_row_kernel<<<dim3(HH, NB), blk, CC_SMEM>>>(pqkv, patt, cc_gm, cb);
            float* tmp = ca; ca = cb; cb = tmp;
        }
    }

    // my attention x2
    {
        float* ma = pmy; float* mb = pt1;
        for (int it = 0; it < 2; it++){
            to_nhwc_kernel<<<dim3(HW/32, 256/32, NB), tr_blk>>>(ma, ACTh, ACTl, 256, 256, 0);
            mma_conv_kernel<<<dim3(NT, 3), blk, MC_SMEM>>>(WQmy, ACTh, ACTl,
                                                           QKVC, 256, 1, 256, 0, pBmy, pqkv);
            gram_kernel<<<256, blk>>>(pqkv, pS);
            myw_kernel<<<1, 32>>>(pS, pWm);
            my_combine_kernel<<<(CMID*HW + 255)/256, blk>>>(pqkv, pWm, ma, my_gm, mb);
            float* tmp = ma; ma = mb; mb = tmp;
        }
    }

    // conv_b: input pcc -> BN -> XC@1024 (fused)
    to_nhwc_kernel<<<dim3(HW/32, 256/32, NB), tr_blk>>>(pcc, ACTh, ACTl, 256, 256, 0);
    mma_conv_kernel<<<dim3(NT, 2), blk, MC_SMEM>>>(WB, ACTh, ACTl, 256, 256, 9, 256, 0, nullptr, pt0);
    bn_stats_kernel<<<CMID, blk>>>(pt0, g_b, b_b, pst, CMID);
    bn_to_nhwc_kernel<<<dim3(HW/32, 256/32, NB), tr_blk>>>(pt0, pst, XCh, XCl, 256, 1536, 1024);

    // conv_m2: input pmy -> BN -> XC@1280 (fused)
    to_nhwc_kernel<<<dim3(HW/32, 256/32, NB), tr_blk>>>(pmy, ACTh, ACTl, 256, 256, 0);
    mma_conv_kernel<<<dim3(NT, 2), blk, MC_SMEM>>>(WM2, ACTh, ACTl, 256, 256, 9, 256, 0, nullptr, pt0);
    bn_stats_kernel<<<CMID, blk>>>(pt0, g_m2, b_m2, pst, CMID);
    bn_to_nhwc_kernel<<<dim3(HW/32, 256/32, NB), tr_blk>>>(pt0, pst, XCh, XCl, 256, 1536, 1280);

    // conv_c + BN
    mma_conv_kernel<<<dim3(NT, 4), blk, MC_SMEM>>>(WC, XCh, XCl, 512, 1536, 9, 1536, 0, nullptr, ph);
    bn_stats_kernel<<<OCH, blk>>>(ph, g_c, b_c, pst, OCH);
    bn_apply_kernel<<<(NB*OCH*HW + 255)/256, blk>>>(ph, pst, ph, OCH, NB*OCH*HW);

    // classifier (dedicated slim kernel)
    cls_kernel<<<NTOT/256, blk>>>(ph, w_cls, b_cls, (float*)d_out);
}

// round 17
// speedup vs baseline: 1.3920x; 1.0376x over previous
#include <cuda_runtime.h>
#include <cuda_fp16.h>
#include <math.h>
#include <stdint.h>

#define NB   16
#define CIN  1024
#define CMID 256
#define C8   32
#define HH   48
#define WW   48
#define HW   (HH*WW)
#define NTOT (NB*HW)
#define OCH  512
#define NCLS 21
#define QKVC 384
#define NEG_INF (__int_as_float(0xff800000))

// ---------------- static scratch ----------------
__device__ float g_t0[NB*CMID*HW];
__device__ float g_cc[NB*CMID*HW];
__device__ float g_my[NB*CMID*HW];
__device__ float g_t1[NB*CMID*HW];
__device__ float g_qkv[(size_t)NB*QKVC*HW];
__device__ float g_h [NB*OCH*HW];
__device__ float g_stats[2*OCH];
__device__ float g_S[256];
__device__ float g_Wm[256];
__device__ float g_att[(size_t)NTOT*96];
__device__ float g_Bcc[QKVC];
__device__ float g_Bmy[QKVC];

__device__ __align__(256) __half g_XCh[(size_t)NTOT*1536];
__device__ __align__(256) __half g_XCl[(size_t)NTOT*1536];
__device__ __align__(256) __half g_ACTh[(size_t)NTOT*256];
__device__ __align__(256) __half g_ACTl[(size_t)NTOT*256];
__device__ __align__(256) __half g_ACT2h[(size_t)NTOT*256];
__device__ __align__(256) __half g_ACT2l[(size_t)NTOT*256];
__device__ __align__(256) __half g_WA [256*9216];
__device__ __align__(256) __half g_WM1[256*9216];
__device__ __align__(256) __half g_WB [256*2304];
__device__ __align__(256) __half g_WM2[256*2304];
__device__ __align__(256) __half g_WC [512*13824];
__device__ __align__(256) __half g_WQcc[QKVC*256];
__device__ __align__(256) __half g_WQmy[QKVC*256];

// ---------------- helpers ----------------
__device__ __forceinline__ uint32_t smem_u32(const void* p){
    uint32_t a;
    asm("{ .reg .u64 t; cvta.to.shared.u64 t, %1; cvt.u32.u64 %0, t; }" : "=r"(a) : "l"(p));
    return a;
}
__device__ __forceinline__ void cp16(uint32_t s, const void* g, uint32_t sz){
    asm volatile("cp.async.cg.shared.global [%0], [%1], 16, %2;" :: "r"(s), "l"(g), "r"(sz) : "memory");
}
__device__ __forceinline__ void ldmx4(uint32_t* r, uint32_t a){
    asm volatile("ldmatrix.sync.aligned.m8n8.x4.shared.b16 {%0,%1,%2,%3}, [%4];"
        : "=r"(r[0]),"=r"(r[1]),"=r"(r[2]),"=r"(r[3]) : "r"(a));
}
__device__ __forceinline__ void mma_f16(float* d, const uint32_t* a, const uint32_t* b){
    asm volatile("mma.sync.aligned.m16n8k16.row.col.f32.f16.f16.f32 "
        "{%0,%1,%2,%3}, {%4,%5,%6,%7}, {%8,%9}, {%0,%1,%2,%3};"
        : "+f"(d[0]),"+f"(d[1]),"+f"(d[2]),"+f"(d[3])
        : "r"(a[0]),"r"(a[1]),"r"(a[2]),"r"(a[3]), "r"(b[0]),"r"(b[1]));
}

// ---------------- NCHW fp32 -> NHWC fp16 hi/lo ----------------
__global__ void to_nhwc_kernel(const float* __restrict__ src,
                               __half* __restrict__ hi,
                               __half* __restrict__ lo,
                               int C, int RS, int co)
{
    __shared__ float t[32][33];
    int hw0 = blockIdx.x * 32, c0 = blockIdx.y * 32, b = blockIdx.z;
    int lx = threadIdx.x, ly = threadIdx.y;
    for (int i = ly; i < 32; i += 8)
        t[i][lx] = src[((size_t)(b * C + c0 + i)) * HW + hw0 + lx];
    __syncthreads();
    for (int i = ly; i < 32; i += 8){
        float v = t[lx][i];
        __half h = __float2half_rn(v);
        size_t o = ((size_t)(b * HW + hw0 + i)) * RS + co + c0 + lx;
        hi[o] = h;
        lo[o] = __float2half_rn(v - __half2float(h));
    }
}

__global__ void bn_to_nhwc_kernel(const float* __restrict__ src,
                                  const float* __restrict__ stats,
                                  __half* __restrict__ hi,
                                  __half* __restrict__ lo,
                                  int C, int RS, int co)
{
    __shared__ float t[32][33];
    int hw0 = blockIdx.x * 32, c0 = blockIdx.y * 32, b = blockIdx.z;
    int lx = threadIdx.x, ly = threadIdx.y;
    for (int i = ly; i < 32; i += 8){
        int c = c0 + i;
        float v = src[((size_t)(b * C + c)) * HW + hw0 + lx];
        t[i][lx] = fmaxf(fmaf(v, stats[2*c], stats[2*c+1]), 0.f);
    }
    __syncthreads();
    for (int i = ly; i < 32; i += 8){
        float v = t[lx][i];
        __half h = __float2half_rn(v);
        size_t o = ((size_t)(b * HW + hw0 + i)) * RS + co + c0 + lx;
        hi[o] = h;
        lo[o] = __float2half_rn(v - __half2float(h));
    }
}

// BN + ReLU -> fp32 NCHW AND NHWC fp16 hi/lo in one pass
__global__ void bn_apply_nhwc_kernel(const float* __restrict__ src,
                                     const float* __restrict__ stats,
                                     float* __restrict__ yf,
                                     __half* __restrict__ hi,
                                     __half* __restrict__ lo)
{
    __shared__ float t[32][33];
    int hw0 = blockIdx.x * 32, c0 = blockIdx.y * 32, b = blockIdx.z;
    int lx = threadIdx.x, ly = threadIdx.y;
    for (int i = ly; i < 32; i += 8){
        int c = c0 + i;
        size_t oi = ((size_t)(b * CMID + c)) * HW + hw0 + lx;
        float v = fmaxf(fmaf(src[oi], stats[2*c], stats[2*c+1]), 0.f);
        t[i][lx] = v;
        yf[oi] = v;
    }
    __syncthreads();
    for (int i = ly; i < 32; i += 8){
        float v = t[lx][i];
        __half h = __float2half_rn(v);
        size_t o = ((size_t)(b * HW + hw0 + i)) * 256 + c0 + lx;
        hi[o] = h;
        lo[o] = __float2half_rn(v - __half2float(h));
    }
}

// ---------------- weight prep (fp16 hi only) ----------------
__global__ void wprep_kernel(const float* __restrict__ w,
                             __half* __restrict__ hi,
                             int M, int C, int ntaps)
{
    int i = blockIdx.x * 256 + threadIdx.x;
    int Kt = ntaps * C;
    if (i < M * Kt){
        int m = i / Kt; int rest = i - m * Kt; int t = rest / C; int c = rest - t * C;
        hi[i] = __float2half_rn(w[(size_t)(m * C + c) * ntaps + t]);
    }
}

__global__ void wprep_qkv_kernel(const float* __restrict__ qw, const float* __restrict__ qb,
                                 const float* __restrict__ kw, const float* __restrict__ kb,
                                 const float* __restrict__ vw, const float* __restrict__ vb,
                                 __half* __restrict__ hi,
                                 float* __restrict__ bias)
{
    int i = blockIdx.x * 256 + threadIdx.x;
    if (i < QKVC * 256){
        int m = i >> 8, c = i & 255;
        float v = 0.f;
        if (m < 32)       v = qw[m * 256 + c];
        else if (m < 64)  v = kw[(m - 32) * 256 + c];
        else if (m < 320) v = vw[(m - 64) * 256 + c];
        hi[i] = __float2half_rn(v);
    }
    if (i < QKVC){
        float bv = 0.f;
        if (i < 32)       bv = qb[i];
        else if (i < 64)  bv = kb[i - 32];
        else if (i < 320) bv = vb[i - 64];
        bias[i] = bv;
    }
}

// ---------------- mma.sync implicit-GEMM conv (fp16, 2-stage) -------
#define MC_BUF  30720
#define MC_SMEM (2*MC_BUF)

struct McCtx {
    const __half *A, *Bh, *Bl;
    int C, ntaps, Ktot, cpT, RS, co, use_lo;
    int r, half, b, yy, xx, am;
    uint32_t sb;
};

__device__ __forceinline__ void mc_load(const McCtx& cx, int cc, int buf)
{
    int t   = cc / cx.cpT;
    int ci0 = (cc - t * cx.cpT) << 5;
    uint32_t dst = cx.sb + buf * MC_BUF + cx.r * 80 + cx.half * 32;
    {
        size_t off = (size_t)cx.am * cx.Ktot + t * cx.C + ci0 + cx.half * 16;
        cp16(dst,      cx.A + off,     16);
        cp16(dst + 16, cx.A + off + 8, 16);
    }
    {
        int dy = 0, dx = 0;
        if (cx.ntaps == 9){ dy = t / 3 - 1; dx = t - (t / 3) * 3 - 1; }
        int ys = cx.yy + dy, xs = cx.xx + dx;
        bool bv = (ys >= 0 && ys < HH && xs >= 0 && xs < WW);
        size_t off = bv ? ((size_t)(cx.b * HW + ys * WW + xs) * cx.RS + cx.co + ci0 + cx.half * 16) : 0;
        uint32_t sz = bv ? 16u : 0u;
        cp16(dst + 10240,      cx.Bh + off,     sz);
        cp16(dst + 10240 + 16, cx.Bh + off + 8, sz);
        if (cx.use_lo){
            cp16(dst + 20480,      cx.Bl + off,     sz);
            cp16(dst + 20480 + 16, cx.Bl + off + 8, sz);
        }
    }
}

__global__ __launch_bounds__(256) void mma_conv_kernel(
    const __half* __restrict__ A,
    const __half* __restrict__ Bh, const __half* __restrict__ Bl,
    int M, int C, int ntaps, int RS, int co, int use_lo,
    const float* __restrict__ bias,
    float* __restrict__ out)
{
    extern __shared__ char dynsm[];
    const int tid = threadIdx.x, lane = tid & 31, wid = tid >> 5;
    const int wm = wid & 1, wn = wid >> 1;
    const int m0 = blockIdx.y * 128;
    const int n0 = blockIdx.x * 128;

    McCtx cx;
    cx.A = A; cx.Bh = Bh; cx.Bl = Bl;
    cx.C = C; cx.ntaps = ntaps; cx.Ktot = ntaps * C; cx.cpT = C >> 5;
    cx.RS = RS; cx.co = co; cx.use_lo = use_lo;
    cx.r = tid >> 1; cx.half = tid & 1;
    {
        int n = n0 + cx.r;
        cx.b = n / HW;
        int hw = n - cx.b * HW;
        cx.yy = hw / WW;
        cx.xx = hw - cx.yy * WW;
    }
    cx.am = m0 + cx.r;
    cx.sb = smem_u32(dynsm);

    float acc[4][4][4];
#pragma unroll
    for (int i = 0; i < 4; i++)
#pragma unroll
        for (int j = 0; j < 4; j++)
#pragma unroll
            for (int q = 0; q < 4; q++) acc[i][j][q] = 0.f;

    const int NC = cx.Ktot >> 5;

    mc_load(cx, 0, 0);
    asm volatile("cp.async.commit_group;" ::: "memory");

    const uint32_t aRowOff = (uint32_t)(lane & 15) * 80;
    const uint32_t aColOff = (uint32_t)(lane >> 4) * 16;
    const uint32_t bRowOff = (uint32_t)((lane & 7) + ((lane >> 4) << 3)) * 80;
    const uint32_t bColOff = (uint32_t)((lane >> 3) & 1) * 16;

    for (int cc = 0; cc < NC; cc++){
        int buf = cc & 1;
        if (cc + 1 < NC){
            mc_load(cx, cc + 1, (cc + 1) & 1);
            asm volatile("cp.async.commit_group;" ::: "memory");
            asm volatile("cp.async.wait_group 1;" ::: "memory");
        } else {
            asm volatile("cp.async.wait_group 0;" ::: "memory");
        }
        __syncthreads();
        uint32_t base = cx.sb + buf * MC_BUF;
#pragma unroll
        for (int k16 = 0; k16 < 2; k16++){
            uint32_t ac = (uint32_t)k16 * 32 + aColOff;
            uint32_t bc = (uint32_t)k16 * 32 + bColOff;
            uint32_t ah[4][4], bh[2][4], bl[2][4];
#pragma unroll
            for (int mi = 0; mi < 4; mi++){
                uint32_t ad = base + (uint32_t)(wm * 64 + mi * 16) * 80 + aRowOff + ac;
                ldmx4(ah[mi], ad);
            }
#pragma unroll
            for (int ng = 0; ng < 2; ng++){
                uint32_t bd = base + 10240 + (uint32_t)(wn * 32 + ng * 16) * 80 + bRowOff + bc;
                ldmx4(bh[ng], bd);
                if (use_lo) ldmx4(bl[ng], bd + 10240);
            }
#pragma unroll
            for (int mi = 0; mi < 4; mi++){
#pragma unroll
                for (int ni = 0; ni < 4; ni++){
                    const uint32_t* bhp = &bh[ni >> 1][(ni & 1) * 2];
                    mma_f16(acc[mi][ni], ah[mi], bhp);
                    if (use_lo){
                        const uint32_t* blp = &bl[ni >> 1][(ni & 1) * 2];
                        mma_f16(acc[mi][ni], ah[mi], blp);
                    }
                }
            }
        }
        __syncthreads();
    }

    int tb = n0 / HW;
    int hw0 = n0 - tb * HW;
#pragma unroll
    for (int mi = 0; mi < 4; mi++){
        int mrow = m0 + wm * 64 + mi * 16 + (lane >> 2);
        float b0 = bias ? __ldg(bias + mrow)     : 0.f;
        float b1 = bias ? __ldg(bias + mrow + 8) : 0.f;
#pragma unroll
        for (int ni = 0; ni < 4; ni++){
            int col = hw0 + wn * 32 + ni * 8 + (lane & 3) * 2;
            float2 v0 = make_float2(acc[mi][ni][0] + b0, acc[mi][ni][1] + b0);
            float2 v1 = make_float2(acc[mi][ni][2] + b1, acc[mi][ni][3] + b1);
            *(float2*)&out[((size_t)(tb * M + mrow)) * HW + col]     = v0;
            *(float2*)&out[((size_t)(tb * M + mrow + 8)) * HW + col] = v1;
        }
    }
}

// ---------------- classifier ----------------
__global__ __launch_bounds__(256) void cls_kernel(
    const float* __restrict__ h, const float* __restrict__ w,
    const float* __restrict__ bias, float* __restrict__ out)
{
    __shared__ float ws[NCLS * OCH];
    int tid = threadIdx.x;
    for (int i = tid; i < NCLS * OCH; i += 256) ws[i] = w[i];
    __syncthreads();
    int n = blockIdx.x * 256 + tid;
    int b = n / HW, hw = n - b * HW;
    float acc[NCLS];
#pragma unroll
    for (int m = 0; m < NCLS; m++) acc[m] = bias[m];
    const float* hp = h + (size_t)b * OCH * HW + hw;
    for (int k = 0; k < OCH; k++){
        float v = hp[(size_t)k * HW];
#pragma unroll
        for (int m = 0; m < NCLS; m++)
            acc[m] = fmaf(v, ws[m * OCH + k], acc[m]);
    }
#pragma unroll
    for (int m = 0; m < NCLS; m++)
        out[((size_t)(b * NCLS + m)) * HW + hw] = acc[m];
}

// ---------------- BatchNorm ----------------
__global__ void bn_stats_kernel(const float* __restrict__ x,
                                const float* __restrict__ g,
                                const float* __restrict__ bta,
                                float* __restrict__ stats, int C)
{
    int c = blockIdx.x, tid = threadIdx.x;
    float s = 0.f, sq = 0.f;
    for (int i = tid; i < NB * HW; i += 256){
        int bb = i / HW;
        float v = x[((size_t)(bb * C + c)) * HW + (i - bb * HW)];
        s += v; sq += v * v;
    }
    __shared__ float sh1[256], sh2[256];
    sh1[tid] = s; sh2[tid] = sq;
    __syncthreads();
    for (int st = 128; st; st >>= 1){
        if (tid < st){ sh1[tid] += sh1[tid + st]; sh2[tid] += sh2[tid + st]; }
        __syncthreads();
    }
    if (tid == 0){
        float n = (float)(NB * HW);
        float m = sh1[0] / n;
        float var = sh2[0] / n - m * m;
        float sc = g[c] * rsqrtf(var + 1e-5f);
        stats[2 * c] = sc;
        stats[2 * c + 1] = bta[c] - m * sc;
    }
}

__global__ void bn_apply_kernel(const float* __restrict__ x,
                                const float* __restrict__ stats,
                                float* __restrict__ y, int C, int total)
{
    int i = blockIdx.x * 256 + threadIdx.x;
    if (i < total){
        int c = (i / HW) % C;
        y[i] = fmaxf(fmaf(x[i], stats[2 * c], stats[2 * c + 1]), 0.f);
    }
}

// ---------------- criss-cross attention ----------------
__global__ void cc_logits_col_kernel(const float* __restrict__ qkv,
                                     float* __restrict__ att)
{
    int w = blockIdx.x, b = blockIdx.y, tid = threadIdx.x;
    __shared__ float qs[32][48], ks[32][48];
    for (int i = tid; i < 32 * 48; i += 256){
        int c = i / 48, h = i - (i / 48) * 48;
        qs[c][h] = qkv[((size_t)((b * QKVC + c) * 48 + h)) * 48 + w];
        ks[c][h] = qkv[((size_t)((b * QKVC + 32 + c) * 48 + h)) * 48 + w];
    }
    __syncthreads();
    for (int i = tid; i < 48 * 48; i += 256){
        int h = i / 48, g = i - (i / 48) * 48;
        float s;
        if (g == h) s = NEG_INF;
        else {
            s = 0.f;
#pragma unroll
            for (int c = 0; c < 32; c++) s += qs[c][h] * ks[c][g];
        }
        att[((size_t)((b * 48 + h) * 48 + w)) * 96 + g] = s;
    }
}

__global__ void cc_logits_row_kernel(const float* __restrict__ qkv,
                                     float* __restrict__ att)
{
    int h = blockIdx.x, b = blockIdx.y, tid = threadIdx.x;
    __shared__ float qs[32][48], ks[32][48];
    for (int i = tid; i < 32 * 48; i += 256){
        int c = i / 48, w = i - (i / 48) * 48;
        qs[c][w] = qkv[((size_t)((b * QKVC + c) * 48 + h)) * 48 + w];
        ks[c][w] = qkv[((size_t)((b * QKVC + 32 + c) * 48 + h)) * 48 + w];
    }
    __syncthreads();
    for (int i = tid; i < 48 * 48; i += 256){
        int w = i / 48, v2 = i - (i / 48) * 48;
        float s = 0.f;
#pragma unroll
        for (int c = 0; c < 32; c++) s += qs[c][w] * ks[c][v2];
        att[((size_t)((b * 48 + h) * 48 + w)) * 96 + 48 + v2] = s;
    }
}

__global__ void cc_softmax_kernel(float* __restrict__ att)
{
    int row  = blockIdx.x * 8 + (threadIdx.x >> 5);
    int lane = threadIdx.x & 31;
    float* p = att + (size_t)row * 96;
    float v0 = p[lane], v1 = p[lane + 32], v2 = p[lane + 64];
    float mx = fmaxf(v0, fmaxf(v1, v2));
#pragma unroll
    for (int off = 16; off; off >>= 1) mx = fmaxf(mx, __shfl_xor_sync(0xffffffff, mx, off));
    float e0 = expf(v0 - mx), e1 = expf(v1 - mx), e2 = expf(v2 - mx);
    float s = e0 + e1 + e2;
#pragma unroll
    for (int off = 16; off; off >>= 1) s += __shfl_xor_sync(0xffffffff, s, off);
    float inv = 1.f / s;
    p[lane] = e0 * inv; p[lane + 32] = e1 * inv; p[lane + 64] = e2 * inv;
}

#define CC_SMEM ((256*48 + 48*48) * 4)

__global__ void cc_out_col_kernel(const float* __restrict__ qkv,
                                  const float* __restrict__ att,
                                  const float* __restrict__ xin,
                                  const float* __restrict__ gamma,
                                  float* __restrict__ out)
{
    extern __shared__ float cs[];
    float* vs = cs; float* as = cs + 256 * 48;
    int w = blockIdx.x, b = blockIdx.y, tid = threadIdx.x;
    for (int i = tid; i < 256 * 48; i += 256){
        int c = i / 48, g = i - (i / 48) * 48;
        vs[i] = qkv[((size_t)((b * QKVC + 64 + c) * 48 + g)) * 48 + w];
    }
    for (int i = tid; i < 48 * 48; i += 256){
        int h = i / 48, g = i - (i / 48) * 48;
        as[i] = att[((size_t)((b * 48 + h) * 48 + w)) * 96 + g];
    }
    __syncthreads();
    float gm = gamma[0];
    for (int i = tid; i < 256 * 48; i += 256){
        int c = i / 48, h = i - (i / 48) * 48;
        float s = 0.f;
#pragma unroll
        for (int g = 0; g < 48; g++) s += vs[c * 48 + g] * as[h * 48 + g];
        size_t o = ((size_t)((b * 256 + c) * 48 + h)) * 48 + w;
        out[o] = xin[o] + gm * s;
    }
}

__global__ void cc_out_row_kernel(const float* __restrict__ qkv,
                                  const float* __restrict__ att,
                                  const float* __restrict__ gamma,
                                  float* __restrict__ out)
{
    extern __shared__ float cs[];
    float* vs = cs; float* as = cs + 256 * 48;
    int h = blockIdx.x, b = blockIdx.y, tid = threadIdx.x;
    for (int i = tid; i < 256 * 48; i += 256){
        vs[i] = qkv[((size_t)(b * QKVC + 64 + i / 48) * 48 + h) * 48 + (i % 48)];
    }
    for (int i = tid; i < 48 * 48; i += 256){
        int w2 = i / 48, v2 = i - (i / 48) * 48;
        as[i] = att[((size_t)((b * 48 + h) * 48 + w2)) * 96 + 48 + v2];
    }
    __syncthreads();
    float gm = gamma[0];
    for (int i = tid; i < 256 * 48; i += 256){
        int c = i / 48, w2 = i - (i / 48) * 48;
        float s = 0.f;
#pragma unroll
        for (int v2 = 0; v2 < 48; v2++) s += vs[c * 48 + v2] * as[w2 * 48 + v2];
        size_t o = ((size_t)((b * 256 + c) * 48 + h)) * 48 + w2;
        out[o] += gm * s;
    }
}

// ---------------- grid attention ----------------
__global__ void gram_kernel(const float* __restrict__ qkv,
                            float* __restrict__ S)
{
    int b1 = blockIdx.x >> 4, b2 = blockIdx.x & 15;
    const float* qp = qkv + (size_t)b1 * (QKVC * HW);
    const float* kp = qkv + (size_t)b2 * (QKVC * HW) + 32 * HW;
    int tid = threadIdx.x;
    float s = 0.f;
    for (int i = tid; i < C8 * HW; i += 256) s += qp[i] * kp[i];
    __shared__ float sh[256];
    sh[tid] = s;
    __syncthreads();
    for (int st = 128; st; st >>= 1){
        if (tid < st) sh[tid] += sh[tid + st];
        __syncthreads();
    }
    if (tid == 0) S[blockIdx.x] = sh[0];
}

__global__ void myw_kernel(const float* __restrict__ S, float* __restrict__ Wm)
{
    int b1 = threadIdx.x;
    if (b1 < 16){
        int gh = b1 >> 2, gw = b1 & 3;
        float l[8];
        for (int j = 0; j < 4; j++){
            int b2 = j * 4 + gw;
            l[j] = (j == gh) ? NEG_INF : S[b1 * 16 + b2];
        }
        for (int j = 0; j < 4; j++) l[4 + j] = S[b1 * 16 + gh * 4 + j];
        float mx = NEG_INF;
        for (int j = 0; j < 8; j++) mx = fmaxf(mx, l[j]);
        float sm = 0.f;
        for (int j = 0; j < 8; j++){ l[j] = expf(l[j] - mx); sm += l[j]; }
        float inv = 1.f / sm;
        float w[16];
        for (int i = 0; i < 16; i++) w[i] = 0.f;
        for (int j = 0; j < 4; j++) w[j * 4 + gw] += l[j] * inv;
        for (int j = 0; j < 4; j++) w[gh * 4 + j] += l[4 + j] * inv;
        for (int i = 0; i < 16; i++) Wm[b1 * 16 + i] = w[i];
    }
}

__global__ void my_combine_kernel(const float* __restrict__ qkv,
                                  const float* __restrict__ Wm,
                                  const float* __restrict__ xin,
                                  const float* __restrict__ gamma,
                                  float* __restrict__ out)
{
    __shared__ float ws[256];
    if (threadIdx.x < 256) ws[threadIdx.x] = Wm[threadIdx.x];
    __syncthreads();
    const int PB = CMID * HW;
    int n = blockIdx.x * 256 + threadIdx.x;
    if (n < PB){
        float vv[16];
#pragma unroll
        for (int b = 0; b < 16; b++)
            vv[b] = qkv[(size_t)b * (QKVC * HW) + 64 * HW + n];
        float gm = gamma[0];
#pragma unroll
        for (int b1 = 0; b1 < 16; b1++){
            float o = 0.f;
#pragma unroll
            for (int b2 = 0; b2 < 16; b2++) o += ws[b1 * 16 + b2] * vv[b2];
            out[(size_t)b1 * PB + n] = gm * o + xin[(size_t)b1 * PB + n];
        }
    }
}

// ---------------- host ----------------
extern "C" void kernel_launch(void* const* d_in, const int* in_sizes, int n_in,
                              void* d_out, int out_size)
{
    const float* x      = (const float*)d_in[0];
    const float* w_a    = (const float*)d_in[1];
    const float* g_a    = (const float*)d_in[2];
    const float* b_a    = (const float*)d_in[3];
    const float* ccq_w  = (const float*)d_in[4];
    const float* ccq_b  = (const float*)d_in[5];
    const float* cck_w  = (const float*)d_in[6];
    const float* cck_b  = (const float*)d_in[7];
    const float* ccv_w  = (const float*)d_in[8];
    const float* ccv_b  = (const float*)d_in[9];
    const float* cc_gm  = (const float*)d_in[10];
    const float* w_b    = (const float*)d_in[11];
    const float* g_b    = (const float*)d_in[12];
    const float* b_b    = (const float*)d_in[13];
    const float* w_m1   = (const float*)d_in[14];
    const float* g_m1   = (const float*)d_in[15];
    const float* b_m1   = (const float*)d_in[16];
    const float* myq_w  = (const float*)d_in[17];
    const float* myq_b  = (const float*)d_in[18];
    const float* myk_w  = (const float*)d_in[19];
    const float* myk_b  = (const float*)d_in[20];
    const float* myv_w  = (const float*)d_in[21];
    const float* myv_b  = (const float*)d_in[22];
    const float* my_gm  = (const float*)d_in[23];
    const float* w_m2   = (const float*)d_in[24];
    const float* g_m2   = (const float*)d_in[25];
    const float* b_m2   = (const float*)d_in[26];
    const float* w_c    = (const float*)d_in[27];
    const float* g_c    = (const float*)d_in[28];
    const float* b_c    = (const float*)d_in[29];
    const float* w_cls  = (const float*)d_in[30];
    const float* b_cls  = (const float*)d_in[31];

    cudaFuncSetAttribute(mma_conv_kernel, cudaFuncAttributeMaxDynamicSharedMemorySize, MC_SMEM);
    cudaFuncSetAttribute(cc_out_col_kernel, cudaFuncAttributeMaxDynamicSharedMemorySize, CC_SMEM);
    cudaFuncSetAttribute(cc_out_row_kernel, cudaFuncAttributeMaxDynamicSharedMemorySize, CC_SMEM);

    float *pt0, *pcc, *pmy, *pt1, *pqkv, *ph, *pst, *pS, *pWm, *patt, *pBcc, *pBmy;
    cudaGetSymbolAddress((void**)&pt0, g_t0);
    cudaGetSymbolAddress((void**)&pcc, g_cc);
    cudaGetSymbolAddress((void**)&pmy, g_my);
    cudaGetSymbolAddress((void**)&pt1, g_t1);
    cudaGetSymbolAddress((void**)&pqkv, g_qkv);
    cudaGetSymbolAddress((void**)&ph,  g_h);
    cudaGetSymbolAddress((void**)&pst, g_stats);
    cudaGetSymbolAddress((void**)&pS,  g_S);
    cudaGetSymbolAddress((void**)&pWm, g_Wm);
    cudaGetSymbolAddress((void**)&patt, g_att);
    cudaGetSymbolAddress((void**)&pBcc, g_Bcc);
    cudaGetSymbolAddress((void**)&pBmy, g_Bmy);

    __half *XCh,*XCl,*ACTh,*ACTl,*ACT2h,*ACT2l;
    __half *WA,*WM1,*WB,*WM2,*WC,*WQcc,*WQmy;
    cudaGetSymbolAddress((void**)&XCh, g_XCh);   cudaGetSymbolAddress((void**)&XCl, g_XCl);
    cudaGetSymbolAddress((void**)&ACTh, g_ACTh); cudaGetSymbolAddress((void**)&ACTl, g_ACTl);
    cudaGetSymbolAddress((void**)&ACT2h, g_ACT2h); cudaGetSymbolAddress((void**)&ACT2l, g_ACT2l);
    cudaGetSymbolAddress((void**)&WA, g_WA);
    cudaGetSymbolAddress((void**)&WM1, g_WM1);
    cudaGetSymbolAddress((void**)&WB, g_WB);
    cudaGetSymbolAddress((void**)&WM2, g_WM2);
    cudaGetSymbolAddress((void**)&WC, g_WC);
    cudaGetSymbolAddress((void**)&WQcc, g_WQcc);
    cudaGetSymbolAddress((void**)&WQmy, g_WQmy);

    const dim3 blk(256);
    const dim3 tr_blk(32, 8);
    const int NT = NTOT / 128;
    const int TOT_MID = NB*CMID*HW;

    // weight prep
    wprep_kernel<<<(256*9216 + 255)/256, blk>>>(w_a,  WA,  256, 1024, 9);
    wprep_kernel<<<(256*9216 + 255)/256, blk>>>(w_m1, WM1, 256, 1024, 9);
    wprep_kernel<<<(256*2304 + 255)/256, blk>>>(w_b,  WB,  256, 256, 9);
    wprep_kernel<<<(256*2304 + 255)/256, blk>>>(w_m2, WM2, 256, 256, 9);
    wprep_kernel<<<(512*13824 + 255)/256, blk>>>(w_c, WC,  512, 1536, 9);
    wprep_qkv_kernel<<<(QKVC*256 + 255)/256, blk>>>(ccq_w, ccq_b, cck_w, cck_b, ccv_w, ccv_b,
                                                    WQcc, pBcc);
    wprep_qkv_kernel<<<(QKVC*256 + 255)/256, blk>>>(myq_w, myq_b, myk_w, myk_b, myv_w, myv_b,
                                                    WQmy, pBmy);

    // x -> XC[0:1024]
    to_nhwc_kernel<<<dim3(HW/32, 1024/32, NB), tr_blk>>>(x, XCh, XCl, 1024, 1536, 0);

    // conv_a -> BN -> pcc + ACT (fused)
    mma_conv_kernel<<<dim3(NT, 2), blk, MC_SMEM>>>(WA, XCh, XCl, 256, 1024, 9, 1536, 0, 1, nullptr, pt0);
    bn_stats_kernel<<<CMID, blk>>>(pt0, g_a, b_a, pst, CMID);
    bn_apply_nhwc_kernel<<<dim3(HW/32, 256/32, NB), tr_blk>>>(pt0, pst, pcc, ACTh, ACTl);

    // conv_m1 -> BN -> pmy + ACT2 (fused)
    mma_conv_kernel<<<dim3(NT, 2), blk, MC_SMEM>>>(WM1, XCh, XCl, 256, 1024, 9, 1536, 0, 1, nullptr, pt0);
    bn_stats_kernel<<<CMID, blk>>>(pt0, g_m1, b_m1, pst, CMID);
    bn_apply_nhwc_kernel<<<dim3(HW/32, 256/32, NB), tr_blk>>>(pt0, pst, pmy, ACT2h, ACT2l);

    // cc attention x2 (iter0 uses prefilled ACT)
    {
        float* ca = pcc; float* cb = pt1;
        for (int it = 0; it < 2; it++){
            if (it > 0)
                to_nhwc_kernel<<<dim3(HW/32, 256/32, NB), tr_blk>>>(ca, ACTh, ACTl, 256, 256, 0);
            mma_conv_kernel<<<dim3(NT, 3), blk, MC_SMEM>>>(WQcc, ACTh, ACTl,
                                                           QKVC, 256, 1, 256, 0, 1, pBcc, pqkv);
            cc_logits_col_kernel<<<dim3(WW, NB), blk>>>(pqkv, patt);
            cc_logits_row_kernel<<<dim3(HH, NB), blk>>>(pqkv, patt);
            cc_softmax_kernel<<<NTOT/8, blk>>>(patt);
            cc_out_col_kernel<<<dim3(WW, NB), blk, CC_SMEM>>>(pqkv, patt, ca, cc_gm, cb);
            cc_out_row_kernel<<<dim3(HH, NB), blk, CC_SMEM>>>(pqkv, patt, cc_gm, cb);
            float* tmp = ca; ca = cb; cb = tmp;
        }
    }

    // my attention x2 (iter0 uses prefilled ACT2; iter1 converts into ACT)
    {
        float* ma = pmy; float* mb = pt1;
        for (int it = 0; it < 2; it++){
            __half *ah = (it == 0) ? ACT2h : ACTh;
            __half *al = (it == 0) ? ACT2l : ACTl;
            if (it > 0)
                to_nhwc_kernel<<<dim3(HW/32, 256/32, NB), tr_blk>>>(ma, ah, al, 256, 256, 0);
            mma_conv_kernel<<<dim3(NT, 3), blk, MC_SMEM>>>(WQmy, ah, al,
                                                           QKVC, 256, 1, 256, 0, 1, pBmy, pqkv);
            gram_kernel<<<256, blk>>>(pqkv, pS);
            myw_kernel<<<1, 32>>>(pS, pWm);
            my_combine_kernel<<<(CMID*HW + 255)/256, blk>>>(pqkv, pWm, ma, my_gm, mb);
            float* tmp = ma; ma = mb; mb = tmp;
        }
    }

    // conv_b: input pcc -> BN -> XC@1024 (fused)
    to_nhwc_kernel<<<dim3(HW/32, 256/32, NB), tr_blk>>>(pcc, ACTh, ACTl, 256, 256, 0);
    mma_conv_kernel<<<dim3(NT, 2), blk, MC_SMEM>>>(WB, ACTh, ACTl, 256, 256, 9, 256, 0, 1, nullptr, pt0);
    bn_stats_kernel<<<CMID, blk>>>(pt0, g_b, b_b, pst, CMID);
    bn_to_nhwc_kernel<<<dim3(HW/32, 256/32, NB), tr_blk>>>(pt0, pst, XCh, XCl, 256, 1536, 1024);

    // conv_m2: input pmy -> BN -> XC@1280 (fused)
    to_nhwc_kernel<<<dim3(HW/32, 256/32, NB), tr_blk>>>(pmy, ACTh, ACTl, 256, 256, 0);
    mma_conv_kernel<<<dim3(NT, 2), blk, MC_SMEM>>>(WM2, ACTh, ACTl, 256, 256, 9, 256, 0, 1, nullptr, pt0);
    bn_stats_kernel<<<CMID, blk>>>(pt0, g_m2, b_m2, pst, CMID);
    bn_to_nhwc_kernel<<<dim3(HW/32, 256/32, NB), tr_blk>>>(pt0, pst, XCh, XCl, 256, 1536, 1280);

    // conv_c + BN  (hi-only: drop activation-lo product)
    mma_conv_kernel<<<dim3(NT, 4), blk, MC_SMEM>>>(WC, XCh, XCl, 512, 1536, 9, 1536, 0, 0, nullptr, ph);
    bn_stats_kernel<<<OCH, blk>>>(ph, g_c, b_c, pst, OCH);
    bn_apply_kernel<<<(NB*OCH*HW + 255)/256, blk>>>(ph, pst, ph, OCH, NB*OCH*HW);

    // classifier
    cls_kernel<<<NTOT/256, blk>>>(ph, w_cls, b_cls, (float*)d_out);
}